// round 8
// baseline (speedup 1.0000x reference)
#include <cuda_runtime.h>
#include <math.h>

// ---------------- problem constants ----------------
#define BB 2
#define TT 2048
#define DD 1024
#define MM (BB*TT)          // 4096 token rows
#define INNER 2048
#define DSTATE 64
#define EE 4
#define HID 4096

// ---------------- scratch (device globals; no allocation allowed) ----------
__device__ float g_h   [MM*DD];        // rmsnorm1 output (tf32-rounded)
__device__ float g_xz  [MM*2*INNER];   // exact
__device__ float g_xm  [MM*INNER];     // exact (epilogue use)
__device__ float g_xmr [MM*INNER];     // tf32-rounded (GEMM A)
__device__ float g_P   [MM*256];       // packed dt|B|C projections (exact)
__device__ float g_y   [MM*DSTATE];    // ln64 output (tf32-rounded)
__device__ float g_y2  [MM*INNER];     // tf32-rounded
__device__ float g_x1  [MM*DD];        // exact
__device__ float g_h2r [MM*DD];        // tf32-rounded (GEMM A)
__device__ float g_wf  [MM*EE];
__device__ float g_hid [MM*HID];       // tf32-rounded
__device__ float g_Wp  [INNER*256];    // packed dt/B/C weights
__device__ float g_bp  [256];
__device__ int   g_idx [EE*MM];
__device__ int   g_cnt [EE];

// ---------------- helpers ----------------
__device__ __forceinline__ float sigmoidf_(float x){ return 1.f/(1.f+expf(-x)); }
__device__ __forceinline__ float rndf(float x){
    unsigned r; asm("cvt.rna.tf32.f32 %0, %1;" : "=r"(r) : "f"(x));
    return __uint_as_float(r);
}
__device__ __forceinline__ unsigned f2tfu(float x){
    unsigned r; asm("cvt.rna.tf32.f32 %0, %1;" : "=r"(r) : "f"(x));
    return r;
}
__device__ __forceinline__ void cpa16(unsigned dst, const void* src){
    asm volatile("cp.async.cg.shared.global [%0], [%1], 16;" :: "r"(dst), "l"(src));
}

// ---------------- rmsnorm (norm1): rounded output ----------------
__global__ void rmsnorm_kernel(const float* __restrict__ x, const float* __restrict__ w,
                               float* __restrict__ out_r)
{
    __shared__ float red[256];
    int row = blockIdx.x, tid = threadIdx.x;
    const float* xr = x + (size_t)row*DD;
    float s = 0.f;
    #pragma unroll
    for (int i = 0; i < DD/256; i++){ float v = xr[tid + i*256]; s += v*v; }
    red[tid] = s; __syncthreads();
    for (int off = 128; off > 0; off >>= 1){ if (tid < off) red[tid] += red[tid+off]; __syncthreads(); }
    float nr = rsqrtf(red[0]/(float)DD + 1e-6f);
    #pragma unroll
    for (int i = 0; i < DD/256; i++){
        int c = tid + i*256;
        out_r[(size_t)row*DD + c] = rndf(xr[c]*nr*w[c]);
    }
}

// ---------------- rmsnorm2 + gating fused ----------------
__global__ void rms2_gate_kernel(const float* __restrict__ x1, const float* __restrict__ w,
                                 const float* __restrict__ gw, const float* __restrict__ gb,
                                 float* __restrict__ h2r, float* __restrict__ wf)
{
    __shared__ float red[256];
    __shared__ float4 red4[256];
    int row = blockIdx.x, tid = threadIdx.x;
    const float* xr = x1 + (size_t)row*DD;
    float s = 0.f;
    #pragma unroll
    for (int i = 0; i < DD/256; i++){ float v = xr[tid + i*256]; s += v*v; }
    red[tid] = s; __syncthreads();
    for (int off = 128; off > 0; off >>= 1){ if (tid < off) red[tid] += red[tid+off]; __syncthreads(); }
    float nr = rsqrtf(red[0]/(float)DD + 1e-6f);
    float p0=0.f,p1=0.f,p2=0.f,p3=0.f;
    #pragma unroll
    for (int i = 0; i < DD/256; i++){
        int c = tid + i*256;
        float v = xr[c]*nr*w[c];
        h2r[(size_t)row*DD + c] = rndf(v);
        const float* g = gw + c*4;
        p0 = fmaf(v, g[0], p0); p1 = fmaf(v, g[1], p1);
        p2 = fmaf(v, g[2], p2); p3 = fmaf(v, g[3], p3);
    }
    red4[tid] = make_float4(p0,p1,p2,p3); __syncthreads();
    for (int off = 128; off > 0; off >>= 1){
        if (tid < off){
            float4 a = red4[tid], b = red4[tid+off];
            red4[tid] = make_float4(a.x+b.x, a.y+b.y, a.z+b.z, a.w+b.w);
        }
        __syncthreads();
    }
    if (tid == 0){
        float l[4] = {red4[0].x+gb[0], red4[0].y+gb[1], red4[0].z+gb[2], red4[0].w+gb[3]};
        int i0 = 0;
        #pragma unroll
        for (int e=1;e<4;e++) if (l[e] > l[i0]) i0 = e;
        int i1 = -1;
        #pragma unroll
        for (int e=0;e<4;e++) if (e != i0 && (i1 < 0 || l[e] > l[i1])) i1 = e;
        float ex = expf(l[i1] - l[i0]);
        float q0 = 1.f/(1.f+ex), q1 = ex/(1.f+ex);
        float wv[4] = {0.f,0.f,0.f,0.f};
        wv[i0]=q0; wv[i1]=q1;
        #pragma unroll
        for (int e=0;e<4;e++) wf[(size_t)row*4+e]=wv[e];
    }
}

// ================= TF32 GEMM, cp.async 3-stage, 128x64x32, 2 CTA/SM ========
// A pre-rounded (raw bits); B converted in-loop via cvt.rna.
// EPI: 0 bias | 1 s2i-gate (rounded store) | 2 residual+dual-store (exact)
//      5 gathered-A gelu (rounded store) | 6 scatter-add (exact accumulate)
#define AS_T 36
#define BS_T 72
#define A_STAGE (128*AS_T)
#define B_STAGE (32*BS_T)
#define NSTAGE 3
#define SMEM_BYTES ((NSTAGE*A_STAGE + NSTAGE*B_STAGE)*4)

template<int EPI>
__device__ __forceinline__ void epi_store(
    float* __restrict__ C, int row, int col, int N, float acc,
    const float* __restrict__ bias,
    const float* __restrict__ ep1, const float* __restrict__ ep2,
    const float* __restrict__ ep3, int ep_stride,
    const int* __restrict__ idx, int cnt)
{
    if ((EPI==5 || EPI==6) && row >= cnt) return;
    float v = acc + bias[col];
    if (EPI == 1) {
        v += ep2[col]*ep1[(size_t)row*N + col];
        v *= sigmoidf_(ep3[(size_t)row*ep_stride + col]);
        v = rndf(v);
    } else if (EPI == 2) {
        v += ep1[(size_t)row*ep_stride + col];
    } else if (EPI == 5) {
        v = 0.5f*v*(1.f + erff(v*0.70710678118654752f));
        v = rndf(v);
    }
    if (EPI == 6) {
        int gr = idx[row];
        C[(size_t)gr*N + col] += ep1[(size_t)gr*4]*v;
    } else {
        C[(size_t)row*N + col] = v;
        if (EPI == 2) ((float*)ep2)[(size_t)row*N + col] = v;   // dual store -> d_out
    }
}

template<int EPI>
__global__ void __launch_bounds__(256, 2) gemm_tf32(
    const float* __restrict__ A, const float* __restrict__ B,
    float* __restrict__ C, int M, int N, int K,
    const float* __restrict__ bias,
    const float* __restrict__ ep1, const float* __restrict__ ep2,
    const float* __restrict__ ep3, int ep_stride,
    const int* __restrict__ idx, const int* __restrict__ cnt_ptr)
{
    extern __shared__ float smem[];
    int tid = threadIdx.x, lane = tid & 31, warp = tid >> 5;
    int wm = (warp >> 1)*32, wn = (warp & 1)*32;   // warp tile 32x32, warps 4x2
    int rowBase = blockIdx.y*128, colBase = blockIdx.x*64;

    int cnt = M;
    if (EPI==5 || EPI==6){
        cnt = *cnt_ptr;
        if (rowBase >= cnt) return;
    }

    // A fill: 128 rows x 32 cols; one row per 2 threads, 16 cols each (4x cp16)
    int ar = tid >> 1;
    int acol = (tid & 1)*16;
    int arow_l = rowBase + ar;
    if (EPI==5 || EPI==6) arow_l = min(arow_l, cnt-1);
    int arow = (EPI==5) ? idx[arow_l] : arow_l;
    const float* aSrc = A + (size_t)arow*K + acol;
    // B fill: 32 rows x 64 cols; one row per 8 threads, 8 cols each (2x cp16)
    int bk = tid >> 3;
    int bcol = (tid & 7)*8;
    const float* bSrc = B + (size_t)bk*N + colBase + bcol;

    unsigned asBase = (unsigned)__cvta_generic_to_shared(smem);
    unsigned bsBase = asBase + NSTAGE*A_STAGE*4;

    float acc[2][4][4];
    #pragma unroll
    for (int i=0;i<2;i++)
        #pragma unroll
        for (int j=0;j<4;j++)
            #pragma unroll
            for (int r=0;r<4;r++) acc[i][j][r]=0.f;

    int nk = K/32;

    // prologue: stages 0,1
    #pragma unroll
    for (int s = 0; s < 2; s++){
        if (s < nk){
            int k0 = s*32;
            unsigned ad = asBase + (s*A_STAGE + ar*AS_T + acol)*4;
            const float* as = aSrc + k0;
            #pragma unroll
            for (int j=0;j<4;j++) cpa16(ad + j*16, as + j*4);
            unsigned bd = bsBase + (s*B_STAGE + bk*BS_T + bcol)*4;
            const float* bs = bSrc + (size_t)k0*N;
            #pragma unroll
            for (int j=0;j<2;j++) cpa16(bd + j*16, bs + j*4);
            asm volatile("cp.async.commit_group;");
        }
    }

    for (int kt = 0; kt < nk; kt++){
        if (kt+2 < nk){
            int stg = (kt+2)%NSTAGE;
            int k0 = (kt+2)*32;
            unsigned ad = asBase + (stg*A_STAGE + ar*AS_T + acol)*4;
            const float* as = aSrc + k0;
            #pragma unroll
            for (int j=0;j<4;j++) cpa16(ad + j*16, as + j*4);
            unsigned bd = bsBase + (stg*B_STAGE + bk*BS_T + bcol)*4;
            const float* bs = bSrc + (size_t)k0*N;
            #pragma unroll
            for (int j=0;j<2;j++) cpa16(bd + j*16, bs + j*4);
            asm volatile("cp.async.commit_group;");
            asm volatile("cp.async.wait_group 2;");
        } else if (kt+1 < nk){
            asm volatile("cp.async.wait_group 1;");
        } else {
            asm volatile("cp.async.wait_group 0;");
        }
        __syncthreads();

        int cur = kt % NSTAGE;
        const float* As = smem + cur*A_STAGE;
        const float* Bs = smem + NSTAGE*A_STAGE + cur*B_STAGE;

        #pragma unroll
        for (int kk = 0; kk < 32; kk += 8){
            unsigned a[2][4], b[4][2];
            int c = kk + (lane&3);
            #pragma unroll
            for (int i=0;i<2;i++){
                int r = wm + i*16 + (lane>>2);
                a[i][0] = __float_as_uint(As[r*AS_T + c]);
                a[i][1] = __float_as_uint(As[(r+8)*AS_T + c]);
                a[i][2] = __float_as_uint(As[r*AS_T + c + 4]);
                a[i][3] = __float_as_uint(As[(r+8)*AS_T + c + 4]);
            }
            #pragma unroll
            for (int j=0;j<4;j++){
                int cb = wn + j*8 + (lane>>2);
                b[j][0] = f2tfu(Bs[c*BS_T + cb]);
                b[j][1] = f2tfu(Bs[(c+4)*BS_T + cb]);
            }
            #pragma unroll
            for (int i=0;i<2;i++)
                #pragma unroll
                for (int j=0;j<4;j++){
                    asm volatile(
                        "mma.sync.aligned.m16n8k8.row.col.f32.tf32.tf32.f32 "
                        "{%0,%1,%2,%3}, {%4,%5,%6,%7}, {%8,%9}, {%0,%1,%2,%3};"
                        : "+f"(acc[i][j][0]), "+f"(acc[i][j][1]),
                          "+f"(acc[i][j][2]), "+f"(acc[i][j][3])
                        : "r"(a[i][0]), "r"(a[i][1]), "r"(a[i][2]), "r"(a[i][3]),
                          "r"(b[j][0]), "r"(b[j][1]));
                }
        }
        __syncthreads();
    }

    #pragma unroll
    for (int i=0;i<2;i++){
        #pragma unroll
        for (int j=0;j<4;j++){
            int r0 = rowBase + wm + i*16 + (lane>>2);
            int c0 = colBase + wn + j*8 + 2*(lane&3);
            epi_store<EPI>(C, r0,   c0,   N, acc[i][j][0], bias, ep1, ep2, ep3, ep_stride, idx, cnt);
            epi_store<EPI>(C, r0,   c0+1, N, acc[i][j][1], bias, ep1, ep2, ep3, ep_stride, idx, cnt);
            epi_store<EPI>(C, r0+8, c0,   N, acc[i][j][2], bias, ep1, ep2, ep3, ep_stride, idx, cnt);
            epi_store<EPI>(C, r0+8, c0+1, N, acc[i][j][3], bias, ep1, ep2, ep3, ep_stride, idx, cnt);
        }
    }
}

// ---------------- pack dt/B/C weights into [INNER, 256] --------------------
__global__ void pack_w_kernel(const float* __restrict__ dtw, const float* __restrict__ bpw,
                              const float* __restrict__ cpw, const float* __restrict__ dtb,
                              const float* __restrict__ bpb, const float* __restrict__ cpb,
                              float* __restrict__ W, float* __restrict__ bias)
{
    int i = blockIdx.x*blockDim.x + threadIdx.x;
    int k = i >> 8, c = i & 255;
    float v = 0.f;
    if      (c < 64)  v = dtw[k*64 + c];
    else if (c < 128) v = bpw[k*64 + c - 64];
    else if (c < 192) v = cpw[k*64 + c - 128];
    W[i] = v;
    if (i < 256){
        float b = 0.f;
        if      (i < 64)  b = dtb[i];
        else if (i < 128) b = bpb[i-64];
        else if (i < 192) b = cpb[i-128];
        bias[i] = b;
    }
}

// ---------------- causal depthwise conv (K=3) + bias + silu ----------------
__global__ void conv_silu_kernel(const float* __restrict__ xz,
                                 const float* __restrict__ cw,
                                 const float* __restrict__ cb,
                                 float* __restrict__ xm, float* __restrict__ xmr)
{
    int idx = blockIdx.x*blockDim.x + threadIdx.x;
    if (idx >= MM*INNER) return;
    int c  = idx & (INNER-1);
    int rt = idx >> 11;
    int t  = rt & (TT-1);
    const float* w = cw + c*3;
    float v = w[2]*xz[(size_t)rt*(2*INNER) + c];
    if (t >= 1) v += w[1]*xz[(size_t)(rt-1)*(2*INNER) + c];
    if (t >= 2) v += w[0]*xz[(size_t)(rt-2)*(2*INNER) + c];
    v += cb[c];
    float s = v * sigmoidf_(v);
    xm [(size_t)rt*INNER + c] = s;
    xmr[(size_t)rt*INNER + c] = rndf(s);
}

// ---------------- selective-scan over packed P [row,256] -------------------
__global__ void scan_kernel(const float* __restrict__ P, float* __restrict__ y)
{
    __shared__ float sA[256], sU[256];
    int bs = blockIdx.x;
    int b = bs >> 6, s = bs & 63;
    int tid = threadIdx.x;
    size_t baseP = (size_t)b*TT*256 + s;
    size_t baseY = (size_t)b*TT*DSTATE + s;
    float a_l[8], u_l[8], c_l[8];
    float A = 1.f, U = 0.f;
    #pragma unroll
    for (int i=0;i<8;i++){
        int t = tid*8 + i;
        size_t off = baseP + (size_t)t*256;
        float d  = sigmoidf_(P[off]);
        float bb = P[off + 64];
        c_l[i] = P[off + 128];
        float a = 1.f - d, u = d*bb;
        a_l[i]=a; u_l[i]=u;
        U = a*U + u;  A = a*A;
    }
    sA[tid]=A; sU[tid]=U; __syncthreads();
    for (int off=1; off<256; off<<=1){
        float pa=1.f, pu=0.f;
        if (tid >= off){ pa = sA[tid-off]; pu = sU[tid-off]; }
        __syncthreads();
        if (tid >= off){ U = A*pu + U; A = A*pa; }
        sA[tid]=A; sU[tid]=U; __syncthreads();
    }
    float state = (tid > 0) ? sU[tid-1] : 0.f;
    #pragma unroll
    for (int i=0;i<8;i++){
        state = a_l[i]*state + u_l[i];
        int t = tid*8 + i;
        y[baseY + (size_t)t*DSTATE] = c_l[i]*state;
    }
}

// ---------------- layernorm over dim 64 (rounded output) -------------------
__global__ void ln64_kernel(float* __restrict__ y)
{
    __shared__ float red[64];
    __shared__ float mu_s, var_s;
    int row = blockIdx.x, tid = threadIdx.x;
    float v = y[(size_t)row*64 + tid];
    red[tid] = v; __syncthreads();
    for (int off=32; off>0; off>>=1){ if (tid<off) red[tid]+=red[tid+off]; __syncthreads(); }
    if (tid==0) mu_s = red[0]/64.f;
    __syncthreads();
    float d = v - mu_s;
    red[tid] = d*d; __syncthreads();
    for (int off=32; off>0; off>>=1){ if (tid<off) red[tid]+=red[tid+off]; __syncthreads(); }
    if (tid==0) var_s = red[0]/64.f;
    __syncthreads();
    y[(size_t)row*64 + tid] = rndf(d * rsqrtf(var_s + 1e-5f));
}

// ---------------- deterministic per-expert row compaction ------------------
__global__ void compact_kernel(const float* __restrict__ wf, int* __restrict__ idxs,
                               int* __restrict__ cnts)
{
    __shared__ int sbuf[256];
    int e = blockIdx.x, tid = threadIdx.x;
    int base = 0;
    for (int chunk = 0; chunk < MM/256; chunk++){
        int row = chunk*256 + tid;
        int p = (wf[(size_t)row*4 + e] > 0.f) ? 1 : 0;
        sbuf[tid] = p; __syncthreads();
        for (int off=1; off<256; off<<=1){
            int v = (tid >= off) ? sbuf[tid-off] : 0;
            __syncthreads();
            sbuf[tid] += v;
            __syncthreads();
        }
        if (p) idxs[(size_t)e*MM + base + sbuf[tid] - 1] = row;
        base += sbuf[255];
        __syncthreads();
    }
    if (tid == 0) cnts[e] = base;
}

// ---------------- host launcher ----------------
static float* sym(const void* s){ void* p=nullptr; cudaGetSymbolAddress(&p, s); return (float*)p; }
static int*   symi(const void* s){ void* p=nullptr; cudaGetSymbolAddress(&p, s); return (int*)p; }

extern "C" void kernel_launch(void* const* d_in, const int* in_sizes, int n_in,
                              void* d_out, int out_size)
{
    const float* x        = (const float*)d_in[0];
    const float* norm1_w  = (const float*)d_in[1];
    const float* norm2_w  = (const float*)d_in[2];
    const float* in_proj_w= (const float*)d_in[3];
    const float* in_proj_b= (const float*)d_in[4];
    const float* conv_w   = (const float*)d_in[5];
    const float* conv_b   = (const float*)d_in[6];
    const float* dt_w     = (const float*)d_in[7];
    const float* dt_b     = (const float*)d_in[8];
    const float* bp_w     = (const float*)d_in[9];
    const float* bp_b     = (const float*)d_in[10];
    const float* cp_w     = (const float*)d_in[11];
    const float* cp_b     = (const float*)d_in[12];
    const float* s2i_w    = (const float*)d_in[13];
    const float* s2i_b    = (const float*)d_in[14];
    const float* D_param  = (const float*)d_in[15];
    const float* out_w    = (const float*)d_in[16];
    const float* out_b    = (const float*)d_in[17];
    const float* gate_w   = (const float*)d_in[18];
    const float* gate_b   = (const float*)d_in[19];
    const float* e_w1     = (const float*)d_in[20];
    const float* e_b1     = (const float*)d_in[21];
    const float* e_w2     = (const float*)d_in[22];
    const float* e_b2     = (const float*)d_in[23];
    float* out = (float*)d_out;

    float* p_h    = sym(g_h);
    float* p_xz   = sym(g_xz);
    float* p_xm   = sym(g_xm);
    float* p_xmr  = sym(g_xmr);
    float* p_P    = sym(g_P);
    float* p_y    = sym(g_y);
    float* p_y2   = sym(g_y2);
    float* p_x1   = sym(g_x1);
    float* p_h2r  = sym(g_h2r);
    float* p_wf   = sym(g_wf);
    float* p_hid  = sym(g_hid);
    float* p_Wp   = sym(g_Wp);
    float* p_bp   = sym(g_bp);
    int*   p_idx  = symi(g_idx);
    int*   p_cnt  = symi(g_cnt);

    cudaFuncSetAttribute(gemm_tf32<0>, cudaFuncAttributeMaxDynamicSharedMemorySize, SMEM_BYTES);
    cudaFuncSetAttribute(gemm_tf32<1>, cudaFuncAttributeMaxDynamicSharedMemorySize, SMEM_BYTES);
    cudaFuncSetAttribute(gemm_tf32<2>, cudaFuncAttributeMaxDynamicSharedMemorySize, SMEM_BYTES);
    cudaFuncSetAttribute(gemm_tf32<5>, cudaFuncAttributeMaxDynamicSharedMemorySize, SMEM_BYTES);
    cudaFuncSetAttribute(gemm_tf32<6>, cudaFuncAttributeMaxDynamicSharedMemorySize, SMEM_BYTES);

    // 0. pack dt/B/C weights
    pack_w_kernel<<<(INNER*256)/256, 256>>>(dt_w, bp_w, cp_w, dt_b, bp_b, cp_b, p_Wp, p_bp);

    // 1. rmsnorm(x) -> h (rounded)
    rmsnorm_kernel<<<MM, 256>>>(x, norm1_w, p_h);

    // 2. xz = h @ in_proj_w + b  [4096,4096] K=1024
    gemm_tf32<0><<<dim3(2*INNER/64, MM/128), 256, SMEM_BYTES>>>(p_h, in_proj_w, p_xz,
        MM, 2*INNER, DD, in_proj_b, nullptr, nullptr, nullptr, 0, nullptr, nullptr);

    // 3. conv + silu -> x_main (exact + rounded)
    conv_silu_kernel<<<(MM*INNER)/256, 256>>>(p_xz, conv_w, conv_b, p_xm, p_xmr);

    // 4. P = xmr @ Wp + bp  [4096,256] K=2048
    gemm_tf32<0><<<dim3(256/64, MM/128), 256, SMEM_BYTES>>>(p_xmr, p_Wp, p_P,
        MM, 256, INNER, p_bp, nullptr, nullptr, nullptr, 0, nullptr, nullptr);

    // 5. selective scan -> y
    scan_kernel<<<BB*DSTATE, 256>>>(p_P, p_y);

    // 6. layernorm over 64 (rounded output)
    ln64_kernel<<<MM, 64>>>(p_y);

    // 7. y2 = (y @ s2i_w + b + D*xm) * sigmoid(gate), rounded  K=64
    gemm_tf32<1><<<dim3(INNER/64, MM/128), 256, SMEM_BYTES>>>(p_y, s2i_w, p_y2,
        MM, INNER, DSTATE, s2i_b, p_xm, D_param, p_xz + INNER, 2*INNER, nullptr, nullptr);

    // 8. x1 = x + (y2 @ out_w + b), dual-stored to x1 AND d_out  K=2048
    gemm_tf32<2><<<dim3(DD/64, MM/128), 256, SMEM_BYTES>>>(p_y2, out_w, p_x1,
        MM, DD, INNER, out_b, x, out, nullptr, DD, nullptr, nullptr);

    // 9. rmsnorm2 + gating fused -> h2r (rounded), wf
    rms2_gate_kernel<<<MM, 256>>>(p_x1, norm2_w, gate_w, gate_b, p_h2r, p_wf);

    // 10. compaction -> idx/cnt
    compact_kernel<<<EE, 256>>>(p_wf, p_idx, p_cnt);

    // 11. per-expert compacted MoE (accumulates into d_out)
    for (int e = 0; e < EE; e++){
        gemm_tf32<5><<<dim3(HID/64, MM/128), 256, SMEM_BYTES>>>(p_h2r, e_w1 + (size_t)e*DD*HID, p_hid,
            MM, HID, DD, e_b1 + (size_t)e*HID, nullptr, nullptr, nullptr, 0,
            p_idx + (size_t)e*MM, p_cnt + e);
        gemm_tf32<6><<<dim3(DD/64, MM/128), 256, SMEM_BYTES>>>(p_hid, e_w2 + (size_t)e*HID*DD, out,
            MM, DD, HID, e_b2 + (size_t)e*DD, p_wf + e, nullptr, nullptr, 0,
            p_idx + (size_t)e*MM, p_cnt + e);
    }
}

// round 9
// speedup vs baseline: 1.3392x; 1.3392x over previous
#include <cuda_runtime.h>
#include <math.h>

// ---------------- problem constants ----------------
#define BB 2
#define TT 2048
#define DD 1024
#define MM (BB*TT)          // 4096 token rows
#define INNER 2048
#define DSTATE 64
#define EE 4
#define HID 4096

// ---------------- scratch (device globals; no allocation allowed) ----------
__device__ float g_h   [MM*DD];        // rmsnorm1 output (tf32-rounded)
__device__ float g_xz  [MM*2*INNER];   // exact
__device__ float g_xm  [MM*INNER];     // exact (epilogue use)
__device__ float g_xmr [MM*INNER];     // tf32-rounded (GEMM A)
__device__ float g_P   [MM*256];       // packed dt|B|C projections (exact)
__device__ float g_y   [MM*DSTATE];    // ln64 output (tf32-rounded)
__device__ float g_y2  [MM*INNER];     // tf32-rounded
__device__ float g_x1  [MM*DD];        // exact
__device__ float g_h2r [MM*DD];        // tf32-rounded (GEMM A)
__device__ float g_wf  [MM*EE];
__device__ float g_hid [MM*HID];       // tf32-rounded
__device__ float g_Wp  [INNER*256];    // packed dt/B/C weights
__device__ float g_bp  [256];
__device__ int   g_idx [EE*MM];
__device__ int   g_cnt [EE];

// ---------------- helpers ----------------
__device__ __forceinline__ float sigmoidf_(float x){ return 1.f/(1.f+expf(-x)); }
__device__ __forceinline__ float rndf(float x){
    unsigned r; asm("cvt.rna.tf32.f32 %0, %1;" : "=r"(r) : "f"(x));
    return __uint_as_float(r);
}
__device__ __forceinline__ unsigned f2tfu(float x){
    unsigned r; asm("cvt.rna.tf32.f32 %0, %1;" : "=r"(r) : "f"(x));
    return r;
}
__device__ __forceinline__ void cpa16(unsigned dst, const void* src){
    asm volatile("cp.async.cg.shared.global [%0], [%1], 16;" :: "r"(dst), "l"(src));
}

// ---------------- rmsnorm (norm1): rounded output ----------------
__global__ void rmsnorm_kernel(const float* __restrict__ x, const float* __restrict__ w,
                               float* __restrict__ out_r)
{
    __shared__ float red[256];
    int row = blockIdx.x, tid = threadIdx.x;
    const float* xr = x + (size_t)row*DD;
    float s = 0.f;
    #pragma unroll
    for (int i = 0; i < DD/256; i++){ float v = xr[tid + i*256]; s += v*v; }
    red[tid] = s; __syncthreads();
    for (int off = 128; off > 0; off >>= 1){ if (tid < off) red[tid] += red[tid+off]; __syncthreads(); }
    float nr = rsqrtf(red[0]/(float)DD + 1e-6f);
    #pragma unroll
    for (int i = 0; i < DD/256; i++){
        int c = tid + i*256;
        out_r[(size_t)row*DD + c] = rndf(xr[c]*nr*w[c]);
    }
}

// ---------------- rmsnorm2 + gating fused ----------------
__global__ void rms2_gate_kernel(const float* __restrict__ x1, const float* __restrict__ w,
                                 const float* __restrict__ gw, const float* __restrict__ gb,
                                 float* __restrict__ h2r, float* __restrict__ wf)
{
    __shared__ float red[256];
    __shared__ float4 red4[256];
    int row = blockIdx.x, tid = threadIdx.x;
    const float* xr = x1 + (size_t)row*DD;
    float s = 0.f;
    #pragma unroll
    for (int i = 0; i < DD/256; i++){ float v = xr[tid + i*256]; s += v*v; }
    red[tid] = s; __syncthreads();
    for (int off = 128; off > 0; off >>= 1){ if (tid < off) red[tid] += red[tid+off]; __syncthreads(); }
    float nr = rsqrtf(red[0]/(float)DD + 1e-6f);
    float p0=0.f,p1=0.f,p2=0.f,p3=0.f;
    #pragma unroll
    for (int i = 0; i < DD/256; i++){
        int c = tid + i*256;
        float v = xr[c]*nr*w[c];
        h2r[(size_t)row*DD + c] = rndf(v);
        const float* g = gw + c*4;
        p0 = fmaf(v, g[0], p0); p1 = fmaf(v, g[1], p1);
        p2 = fmaf(v, g[2], p2); p3 = fmaf(v, g[3], p3);
    }
    red4[tid] = make_float4(p0,p1,p2,p3); __syncthreads();
    for (int off = 128; off > 0; off >>= 1){
        if (tid < off){
            float4 a = red4[tid], b = red4[tid+off];
            red4[tid] = make_float4(a.x+b.x, a.y+b.y, a.z+b.z, a.w+b.w);
        }
        __syncthreads();
    }
    if (tid == 0){
        float l[4] = {red4[0].x+gb[0], red4[0].y+gb[1], red4[0].z+gb[2], red4[0].w+gb[3]};
        int i0 = 0;
        #pragma unroll
        for (int e=1;e<4;e++) if (l[e] > l[i0]) i0 = e;
        int i1 = -1;
        #pragma unroll
        for (int e=0;e<4;e++) if (e != i0 && (i1 < 0 || l[e] > l[i1])) i1 = e;
        float ex = expf(l[i1] - l[i0]);
        float q0 = 1.f/(1.f+ex), q1 = ex/(1.f+ex);
        float wv[4] = {0.f,0.f,0.f,0.f};
        wv[i0]=q0; wv[i1]=q1;
        #pragma unroll
        for (int e=0;e<4;e++) wf[(size_t)row*4+e]=wv[e];
    }
}

// ======= TF32 GEMM, cp.async 2-stage, 128x128x32 tile, 2 CTA/SM ============
// A pre-rounded (raw bits); B converted in-loop via cvt.rna.
// EPI: 0 bias | 1 s2i-gate (rounded store) | 2 residual+dual-store (exact)
//      5 gathered-A gelu (rounded store) | 6 scatter-add (exact accumulate)
#define AS_T 36
#define BS_T 136
#define A_STAGE (128*AS_T)
#define B_STAGE (32*BS_T)
#define NSTAGE 2
#define SMEM_BYTES ((NSTAGE*A_STAGE + NSTAGE*B_STAGE)*4)

template<int EPI>
__device__ __forceinline__ void epi_store(
    float* __restrict__ C, int row, int col, int N, float acc,
    const float* __restrict__ bias,
    const float* __restrict__ ep1, const float* __restrict__ ep2,
    const float* __restrict__ ep3, int ep_stride,
    const int* __restrict__ idx, int cnt)
{
    if ((EPI==5 || EPI==6) && row >= cnt) return;
    float v = acc + bias[col];
    if (EPI == 1) {
        v += ep2[col]*ep1[(size_t)row*N + col];
        v *= sigmoidf_(ep3[(size_t)row*ep_stride + col]);
        v = rndf(v);
    } else if (EPI == 2) {
        v += ep1[(size_t)row*ep_stride + col];
    } else if (EPI == 5) {
        v = 0.5f*v*(1.f + erff(v*0.70710678118654752f));
        v = rndf(v);
    }
    if (EPI == 6) {
        int gr = idx[row];
        C[(size_t)gr*N + col] += ep1[(size_t)gr*4]*v;
    } else {
        C[(size_t)row*N + col] = v;
        if (EPI == 2) ((float*)ep2)[(size_t)row*N + col] = v;   // dual store -> d_out
    }
}

template<int EPI>
__global__ void __launch_bounds__(256, 2) gemm_tf32(
    const float* __restrict__ A, const float* __restrict__ B,
    float* __restrict__ C, int M, int N, int K,
    const float* __restrict__ bias,
    const float* __restrict__ ep1, const float* __restrict__ ep2,
    const float* __restrict__ ep3, int ep_stride,
    const int* __restrict__ idx, const int* __restrict__ cnt_ptr)
{
    extern __shared__ float smem[];
    int tid = threadIdx.x, lane = tid & 31, warp = tid >> 5;
    int wm = (warp >> 2)*64, wn = (warp & 3)*32;   // warp tile 64x32
    int rowBase = blockIdx.y*128, colBase = blockIdx.x*128;

    int cnt = M;
    if (EPI==5 || EPI==6){
        cnt = *cnt_ptr;
        if (rowBase >= cnt) return;
    }

    // A fill: 128 rows x 32 cols; one row per 2 threads, 16 cols each (4x cp16)
    int ar = tid >> 1;
    int acol = (tid & 1)*16;
    int arow_l = rowBase + ar;
    if (EPI==5 || EPI==6) arow_l = min(arow_l, cnt-1);
    int arow = (EPI==5) ? idx[arow_l] : arow_l;
    const float* aSrc = A + (size_t)arow*K + acol;
    // B fill: 32 rows x 128 cols; one row per 8 threads, 4x16B strided chunks
    int bk = tid >> 3;
    int bcol = (tid & 7)*4;
    const float* bSrc = B + (size_t)bk*N + colBase + bcol;

    unsigned asBase = (unsigned)__cvta_generic_to_shared(smem);
    unsigned bsBase = asBase + NSTAGE*A_STAGE*4;

    float acc[4][4][4];
    #pragma unroll
    for (int i=0;i<4;i++)
        #pragma unroll
        for (int j=0;j<4;j++)
            #pragma unroll
            for (int r=0;r<4;r++) acc[i][j][r]=0.f;

    int nk = K/32;

    // prologue: stage 0
    {
        unsigned ad = asBase + (ar*AS_T + acol)*4;
        #pragma unroll
        for (int j=0;j<4;j++) cpa16(ad + j*16, aSrc + j*4);
        unsigned bd = bsBase + (bk*BS_T + bcol)*4;
        #pragma unroll
        for (int j=0;j<4;j++) cpa16(bd + j*128, bSrc + j*32);
        asm volatile("cp.async.commit_group;");
    }

    for (int kt = 0; kt < nk; kt++){
        int cur = kt & 1;
        if (kt+1 < nk){
            int nxt = 1 - cur;
            int k0 = (kt+1)*32;
            unsigned ad = asBase + (nxt*A_STAGE + ar*AS_T + acol)*4;
            const float* as = aSrc + k0;
            #pragma unroll
            for (int j=0;j<4;j++) cpa16(ad + j*16, as + j*4);
            unsigned bd = bsBase + (nxt*B_STAGE + bk*BS_T + bcol)*4;
            const float* bs = bSrc + (size_t)k0*N;
            #pragma unroll
            for (int j=0;j<4;j++) cpa16(bd + j*128, bs + j*32);
            asm volatile("cp.async.commit_group;");
            asm volatile("cp.async.wait_group 1;");
        } else {
            asm volatile("cp.async.wait_group 0;");
        }
        __syncthreads();

        const float* As = smem + cur*A_STAGE;
        const float* Bs = smem + NSTAGE*A_STAGE + cur*B_STAGE;

        #pragma unroll
        for (int kk = 0; kk < 32; kk += 8){
            unsigned a[4][4], b[4][2];
            int c = kk + (lane&3);
            #pragma unroll
            for (int i=0;i<4;i++){
                int r = wm + i*16 + (lane>>2);
                a[i][0] = __float_as_uint(As[r*AS_T + c]);
                a[i][1] = __float_as_uint(As[(r+8)*AS_T + c]);
                a[i][2] = __float_as_uint(As[r*AS_T + c + 4]);
                a[i][3] = __float_as_uint(As[(r+8)*AS_T + c + 4]);
            }
            #pragma unroll
            for (int j=0;j<4;j++){
                int cb = wn + j*8 + (lane>>2);
                b[j][0] = f2tfu(Bs[c*BS_T + cb]);
                b[j][1] = f2tfu(Bs[(c+4)*BS_T + cb]);
            }
            #pragma unroll
            for (int i=0;i<4;i++)
                #pragma unroll
                for (int j=0;j<4;j++){
                    asm volatile(
                        "mma.sync.aligned.m16n8k8.row.col.f32.tf32.tf32.f32 "
                        "{%0,%1,%2,%3}, {%4,%5,%6,%7}, {%8,%9}, {%0,%1,%2,%3};"
                        : "+f"(acc[i][j][0]), "+f"(acc[i][j][1]),
                          "+f"(acc[i][j][2]), "+f"(acc[i][j][3])
                        : "r"(a[i][0]), "r"(a[i][1]), "r"(a[i][2]), "r"(a[i][3]),
                          "r"(b[j][0]), "r"(b[j][1]));
                }
        }
        __syncthreads();
    }

    #pragma unroll
    for (int i=0;i<4;i++){
        #pragma unroll
        for (int j=0;j<4;j++){
            int r0 = rowBase + wm + i*16 + (lane>>2);
            int c0 = colBase + wn + j*8 + 2*(lane&3);
            epi_store<EPI>(C, r0,   c0,   N, acc[i][j][0], bias, ep1, ep2, ep3, ep_stride, idx, cnt);
            epi_store<EPI>(C, r0,   c0+1, N, acc[i][j][1], bias, ep1, ep2, ep3, ep_stride, idx, cnt);
            epi_store<EPI>(C, r0+8, c0,   N, acc[i][j][2], bias, ep1, ep2, ep3, ep_stride, idx, cnt);
            epi_store<EPI>(C, r0+8, c0+1, N, acc[i][j][3], bias, ep1, ep2, ep3, ep_stride, idx, cnt);
        }
    }
}

// ---------------- pack dt/B/C weights into [INNER, 256] --------------------
__global__ void pack_w_kernel(const float* __restrict__ dtw, const float* __restrict__ bpw,
                              const float* __restrict__ cpw, const float* __restrict__ dtb,
                              const float* __restrict__ bpb, const float* __restrict__ cpb,
                              float* __restrict__ W, float* __restrict__ bias)
{
    int i = blockIdx.x*blockDim.x + threadIdx.x;
    int k = i >> 8, c = i & 255;
    float v = 0.f;
    if      (c < 64)  v = dtw[k*64 + c];
    else if (c < 128) v = bpw[k*64 + c - 64];
    else if (c < 192) v = cpw[k*64 + c - 128];
    W[i] = v;
    if (i < 256){
        float b = 0.f;
        if      (i < 64)  b = dtb[i];
        else if (i < 128) b = bpb[i-64];
        else if (i < 192) b = cpb[i-128];
        bias[i] = b;
    }
}

// ---------------- causal depthwise conv (K=3) + bias + silu ----------------
__global__ void conv_silu_kernel(const float* __restrict__ xz,
                                 const float* __restrict__ cw,
                                 const float* __restrict__ cb,
                                 float* __restrict__ xm, float* __restrict__ xmr)
{
    int idx = blockIdx.x*blockDim.x + threadIdx.x;
    if (idx >= MM*INNER) return;
    int c  = idx & (INNER-1);
    int rt = idx >> 11;
    int t  = rt & (TT-1);
    const float* w = cw + c*3;
    float v = w[2]*xz[(size_t)rt*(2*INNER) + c];
    if (t >= 1) v += w[1]*xz[(size_t)(rt-1)*(2*INNER) + c];
    if (t >= 2) v += w[0]*xz[(size_t)(rt-2)*(2*INNER) + c];
    v += cb[c];
    float s = v * sigmoidf_(v);
    xm [(size_t)rt*INNER + c] = s;
    xmr[(size_t)rt*INNER + c] = rndf(s);
}

// ---------------- selective-scan over packed P [row,256] -------------------
__global__ void scan_kernel(const float* __restrict__ P, float* __restrict__ y)
{
    __shared__ float sA[256], sU[256];
    int bs = blockIdx.x;
    int b = bs >> 6, s = bs & 63;
    int tid = threadIdx.x;
    size_t baseP = (size_t)b*TT*256 + s;
    size_t baseY = (size_t)b*TT*DSTATE + s;
    float a_l[8], u_l[8], c_l[8];
    float A = 1.f, U = 0.f;
    #pragma unroll
    for (int i=0;i<8;i++){
        int t = tid*8 + i;
        size_t off = baseP + (size_t)t*256;
        float d  = sigmoidf_(P[off]);
        float bb = P[off + 64];
        c_l[i] = P[off + 128];
        float a = 1.f - d, u = d*bb;
        a_l[i]=a; u_l[i]=u;
        U = a*U + u;  A = a*A;
    }
    sA[tid]=A; sU[tid]=U; __syncthreads();
    for (int off=1; off<256; off<<=1){
        float pa=1.f, pu=0.f;
        if (tid >= off){ pa = sA[tid-off]; pu = sU[tid-off]; }
        __syncthreads();
        if (tid >= off){ U = A*pu + U; A = A*pa; }
        sA[tid]=A; sU[tid]=U; __syncthreads();
    }
    float state = (tid > 0) ? sU[tid-1] : 0.f;
    #pragma unroll
    for (int i=0;i<8;i++){
        state = a_l[i]*state + u_l[i];
        int t = tid*8 + i;
        y[baseY + (size_t)t*DSTATE] = c_l[i]*state;
    }
}

// ---------------- layernorm over dim 64 (rounded output) -------------------
__global__ void ln64_kernel(float* __restrict__ y)
{
    __shared__ float red[64];
    __shared__ float mu_s, var_s;
    int row = blockIdx.x, tid = threadIdx.x;
    float v = y[(size_t)row*64 + tid];
    red[tid] = v; __syncthreads();
    for (int off=32; off>0; off>>=1){ if (tid<off) red[tid]+=red[tid+off]; __syncthreads(); }
    if (tid==0) mu_s = red[0]/64.f;
    __syncthreads();
    float d = v - mu_s;
    red[tid] = d*d; __syncthreads();
    for (int off=32; off>0; off>>=1){ if (tid<off) red[tid]+=red[tid+off]; __syncthreads(); }
    if (tid==0) var_s = red[0]/64.f;
    __syncthreads();
    y[(size_t)row*64 + tid] = rndf(d * rsqrtf(var_s + 1e-5f));
}

// ---------------- deterministic per-expert row compaction ------------------
__global__ void compact_kernel(const float* __restrict__ wf, int* __restrict__ idxs,
                               int* __restrict__ cnts)
{
    __shared__ int sbuf[256];
    int e = blockIdx.x, tid = threadIdx.x;
    int base = 0;
    for (int chunk = 0; chunk < MM/256; chunk++){
        int row = chunk*256 + tid;
        int p = (wf[(size_t)row*4 + e] > 0.f) ? 1 : 0;
        sbuf[tid] = p; __syncthreads();
        for (int off=1; off<256; off<<=1){
            int v = (tid >= off) ? sbuf[tid-off] : 0;
            __syncthreads();
            sbuf[tid] += v;
            __syncthreads();
        }
        if (p) idxs[(size_t)e*MM + base + sbuf[tid] - 1] = row;
        base += sbuf[255];
        __syncthreads();
    }
    if (tid == 0) cnts[e] = base;
}

// ---------------- host launcher ----------------
static float* sym(const void* s){ void* p=nullptr; cudaGetSymbolAddress(&p, s); return (float*)p; }
static int*   symi(const void* s){ void* p=nullptr; cudaGetSymbolAddress(&p, s); return (int*)p; }

extern "C" void kernel_launch(void* const* d_in, const int* in_sizes, int n_in,
                              void* d_out, int out_size)
{
    const float* x        = (const float*)d_in[0];
    const float* norm1_w  = (const float*)d_in[1];
    const float* norm2_w  = (const float*)d_in[2];
    const float* in_proj_w= (const float*)d_in[3];
    const float* in_proj_b= (const float*)d_in[4];
    const float* conv_w   = (const float*)d_in[5];
    const float* conv_b   = (const float*)d_in[6];
    const float* dt_w     = (const float*)d_in[7];
    const float* dt_b     = (const float*)d_in[8];
    const float* bp_w     = (const float*)d_in[9];
    const float* bp_b     = (const float*)d_in[10];
    const float* cp_w     = (const float*)d_in[11];
    const float* cp_b     = (const float*)d_in[12];
    const float* s2i_w    = (const float*)d_in[13];
    const float* s2i_b    = (const float*)d_in[14];
    const float* D_param  = (const float*)d_in[15];
    const float* out_w    = (const float*)d_in[16];
    const float* out_b    = (const float*)d_in[17];
    const float* gate_w   = (const float*)d_in[18];
    const float* gate_b   = (const float*)d_in[19];
    const float* e_w1     = (const float*)d_in[20];
    const float* e_b1     = (const float*)d_in[21];
    const float* e_w2     = (const float*)d_in[22];
    const float* e_b2     = (const float*)d_in[23];
    float* out = (float*)d_out;

    float* p_h    = sym(g_h);
    float* p_xz   = sym(g_xz);
    float* p_xm   = sym(g_xm);
    float* p_xmr  = sym(g_xmr);
    float* p_P    = sym(g_P);
    float* p_y    = sym(g_y);
    float* p_y2   = sym(g_y2);
    float* p_x1   = sym(g_x1);
    float* p_h2r  = sym(g_h2r);
    float* p_wf   = sym(g_wf);
    float* p_hid  = sym(g_hid);
    float* p_Wp   = sym(g_Wp);
    float* p_bp   = sym(g_bp);
    int*   p_idx  = symi(g_idx);
    int*   p_cnt  = symi(g_cnt);

    cudaFuncSetAttribute(gemm_tf32<0>, cudaFuncAttributeMaxDynamicSharedMemorySize, SMEM_BYTES);
    cudaFuncSetAttribute(gemm_tf32<1>, cudaFuncAttributeMaxDynamicSharedMemorySize, SMEM_BYTES);
    cudaFuncSetAttribute(gemm_tf32<2>, cudaFuncAttributeMaxDynamicSharedMemorySize, SMEM_BYTES);
    cudaFuncSetAttribute(gemm_tf32<5>, cudaFuncAttributeMaxDynamicSharedMemorySize, SMEM_BYTES);
    cudaFuncSetAttribute(gemm_tf32<6>, cudaFuncAttributeMaxDynamicSharedMemorySize, SMEM_BYTES);

    // 0. pack dt/B/C weights
    pack_w_kernel<<<(INNER*256)/256, 256>>>(dt_w, bp_w, cp_w, dt_b, bp_b, cp_b, p_Wp, p_bp);

    // 1. rmsnorm(x) -> h (rounded)
    rmsnorm_kernel<<<MM, 256>>>(x, norm1_w, p_h);

    // 2. xz = h @ in_proj_w + b  [4096,4096] K=1024
    gemm_tf32<0><<<dim3(2*INNER/128, MM/128), 256, SMEM_BYTES>>>(p_h, in_proj_w, p_xz,
        MM, 2*INNER, DD, in_proj_b, nullptr, nullptr, nullptr, 0, nullptr, nullptr);

    // 3. conv + silu -> x_main (exact + rounded)
    conv_silu_kernel<<<(MM*INNER)/256, 256>>>(p_xz, conv_w, conv_b, p_xm, p_xmr);

    // 4. P = xmr @ Wp + bp  [4096,256] K=2048
    gemm_tf32<0><<<dim3(256/128, MM/128), 256, SMEM_BYTES>>>(p_xmr, p_Wp, p_P,
        MM, 256, INNER, p_bp, nullptr, nullptr, nullptr, 0, nullptr, nullptr);

    // 5. selective scan -> y
    scan_kernel<<<BB*DSTATE, 256>>>(p_P, p_y);

    // 6. layernorm over 64 (rounded output)
    ln64_kernel<<<MM, 64>>>(p_y);

    // 7. y2 = (y @ s2i_w + b + D*xm) * sigmoid(gate), rounded  K=64
    gemm_tf32<1><<<dim3(INNER/128, MM/128), 256, SMEM_BYTES>>>(p_y, s2i_w, p_y2,
        MM, INNER, DSTATE, s2i_b, p_xm, D_param, p_xz + INNER, 2*INNER, nullptr, nullptr);

    // 8. x1 = x + (y2 @ out_w + b), dual-stored to x1 AND d_out  K=2048
    gemm_tf32<2><<<dim3(DD/128, MM/128), 256, SMEM_BYTES>>>(p_y2, out_w, p_x1,
        MM, DD, INNER, out_b, x, out, nullptr, DD, nullptr, nullptr);

    // 9. rmsnorm2 + gating fused -> h2r (rounded), wf
    rms2_gate_kernel<<<MM, 256>>>(p_x1, norm2_w, gate_w, gate_b, p_h2r, p_wf);

    // 10. compaction -> idx/cnt
    compact_kernel<<<EE, 256>>>(p_wf, p_idx, p_cnt);

    // 11. per-expert compacted MoE (accumulates into d_out)
    for (int e = 0; e < EE; e++){
        gemm_tf32<5><<<dim3(HID/128, MM/128), 256, SMEM_BYTES>>>(p_h2r, e_w1 + (size_t)e*DD*HID, p_hid,
            MM, HID, DD, e_b1 + (size_t)e*HID, nullptr, nullptr, nullptr, 0,
            p_idx + (size_t)e*MM, p_cnt + e);
        gemm_tf32<6><<<dim3(DD/128, MM/128), 256, SMEM_BYTES>>>(p_hid, e_w2 + (size_t)e*HID*DD, out,
            MM, DD, HID, e_b2 + (size_t)e*DD, p_wf + e, nullptr, nullptr, 0,
            p_idx + (size_t)e*MM, p_cnt + e);
    }
}

// round 11
// speedup vs baseline: 1.8648x; 1.3925x over previous
#include <cuda_runtime.h>
#include <cuda_fp16.h>
#include <math.h>

// ---------------- problem constants ----------------
#define BB 2
#define TT 2048
#define DD 1024
#define MM (BB*TT)          // 4096 token rows
#define INNER 2048
#define DSTATE 64
#define EE 4
#define HID 4096

// ---------------- scratch (device globals; no allocation allowed) ----------
__device__ __half g_hh  [MM*DD];        // rmsnorm1 output (fp16)
__device__ float  g_xz  [MM*2*INNER];   // exact
__device__ float  g_xm  [MM*INNER];     // exact (epilogue use)
__device__ __half g_xmh [MM*INNER];     // fp16 (GEMM A)
__device__ float  g_P   [MM*256];       // packed dt|B|C projections (exact)
__device__ float  g_y   [MM*DSTATE];    // scan output (float)
__device__ __half g_yh  [MM*DSTATE];    // ln64 output (fp16)
__device__ __half g_y2h [MM*INNER];     // fp16
__device__ float  g_x1  [MM*DD];        // exact
__device__ __half g_h2h [MM*DD];        // fp16 (GEMM A)
__device__ float  g_wf  [MM*EE];
__device__ __half g_hid [MM*HID];       // fp16
__device__ int    g_idx [EE*MM];
__device__ int    g_cnt [EE];
// fp16 k-pair-interleaved weights: word[p*N+n] = {W[2p][n], W[2p+1][n]}
__device__ __half2 g_wWp [(INNER/2)*256];
__device__ float   g_bp  [256];
__device__ __half2 g_wIn [(DD/2)*(2*INNER)];
__device__ __half2 g_wS2i[(DSTATE/2)*INNER];
__device__ __half2 g_wOut[(INNER/2)*DD];
__device__ __half2 g_wE1 [(EE*DD/2)*HID];
__device__ __half2 g_wE2 [(EE*HID/2)*DD];

// ---------------- helpers ----------------
__device__ __forceinline__ float sigmoidf_(float x){ return 1.f/(1.f+expf(-x)); }
__device__ __forceinline__ void cpa16(unsigned dst, const void* src){
    asm volatile("cp.async.cg.shared.global [%0], [%1], 16;" :: "r"(dst), "l"(src));
}

// ---------------- weight conversion: f32 [K][N] -> half2 interleaved -------
__global__ void cvtw_kernel(const float* __restrict__ W, __half2* __restrict__ out,
                            int nwords, int N)
{
    int i = blockIdx.x*blockDim.x + threadIdx.x;
    if (i >= nwords) return;
    int p = i / N, n = i - p*N;
    out[i] = __floats2half2_rn(W[(size_t)(2*p)*N + n], W[(size_t)(2*p+1)*N + n]);
}

// ---------------- rmsnorm (norm1): fp16 output ----------------
__global__ void rmsnorm_kernel(const float* __restrict__ x, const float* __restrict__ w,
                               __half* __restrict__ out_h)
{
    __shared__ float red[256];
    int row = blockIdx.x, tid = threadIdx.x;
    const float* xr = x + (size_t)row*DD;
    float s = 0.f;
    #pragma unroll
    for (int i = 0; i < DD/256; i++){ float v = xr[tid + i*256]; s += v*v; }
    red[tid] = s; __syncthreads();
    for (int off = 128; off > 0; off >>= 1){ if (tid < off) red[tid] += red[tid+off]; __syncthreads(); }
    float nr = rsqrtf(red[0]/(float)DD + 1e-6f);
    #pragma unroll
    for (int i = 0; i < DD/256; i++){
        int c = tid + i*256;
        out_h[(size_t)row*DD + c] = __float2half_rn(xr[c]*nr*w[c]);
    }
}

// ---------------- rmsnorm2 + gating fused (fp16 h2 + wf) -------------------
__global__ void rms2_gate_kernel(const float* __restrict__ x1, const float* __restrict__ w,
                                 const float* __restrict__ gw, const float* __restrict__ gb,
                                 __half* __restrict__ h2h, float* __restrict__ wf)
{
    __shared__ float red[256];
    __shared__ float4 red4[256];
    int row = blockIdx.x, tid = threadIdx.x;
    const float* xr = x1 + (size_t)row*DD;
    float s = 0.f;
    #pragma unroll
    for (int i = 0; i < DD/256; i++){ float v = xr[tid + i*256]; s += v*v; }
    red[tid] = s; __syncthreads();
    for (int off = 128; off > 0; off >>= 1){ if (tid < off) red[tid] += red[tid+off]; __syncthreads(); }
    float nr = rsqrtf(red[0]/(float)DD + 1e-6f);
    float p0=0.f,p1=0.f,p2=0.f,p3=0.f;
    #pragma unroll
    for (int i = 0; i < DD/256; i++){
        int c = tid + i*256;
        float v = xr[c]*nr*w[c];
        h2h[(size_t)row*DD + c] = __float2half_rn(v);
        const float* g = gw + c*4;
        p0 = fmaf(v, g[0], p0); p1 = fmaf(v, g[1], p1);
        p2 = fmaf(v, g[2], p2); p3 = fmaf(v, g[3], p3);
    }
    red4[tid] = make_float4(p0,p1,p2,p3); __syncthreads();
    for (int off = 128; off > 0; off >>= 1){
        if (tid < off){
            float4 a = red4[tid], b = red4[tid+off];
            red4[tid] = make_float4(a.x+b.x, a.y+b.y, a.z+b.z, a.w+b.w);
        }
        __syncthreads();
    }
    if (tid == 0){
        float l[4] = {red4[0].x+gb[0], red4[0].y+gb[1], red4[0].z+gb[2], red4[0].w+gb[3]};
        int i0 = 0;
        #pragma unroll
        for (int e=1;e<4;e++) if (l[e] > l[i0]) i0 = e;
        int i1 = -1;
        #pragma unroll
        for (int e=0;e<4;e++) if (e != i0 && (i1 < 0 || l[e] > l[i1])) i1 = e;
        float ex = expf(l[i1] - l[i0]);
        float q0 = 1.f/(1.f+ex), q1 = ex/(1.f+ex);
        float wv[4] = {0.f,0.f,0.f,0.f};
        wv[i0]=q0; wv[i1]=q1;
        #pragma unroll
        for (int e=0;e<4;e++) wf[(size_t)row*4+e]=wv[e];
    }
}

// ======= FP16 GEMM (m16n8k16), cp.async 3-stage, 128x128x64, 2 CTA/SM ======
// EPI: 0 bias->f32 | 1 s2i-gate->f16 | 2 residual+dual-store->f32
//      5 gathered-A gelu->f16 | 6 scatter-add->f32
#define KT 64                 // k-tile (halves)
#define AS_TH 72              // A row stride (halves)
#define AS_TW 36              // A row stride (words)
#define BS_TW 136             // B pair-row stride (words)
#define A_STAGE_B (128*AS_TH*2)   // 18432 B
#define B_STAGE_B (32*BS_TW*4)    // 17408 B
#define NSTAGE 3
#define SMEM_BYTES (NSTAGE*(A_STAGE_B + B_STAGE_B))   // 107520 B

template<int EPI>
__device__ __forceinline__ void epi_store(
    void* __restrict__ Cv, int row, int col, int N, float acc,
    const float* __restrict__ bias,
    const float* __restrict__ ep1, const float* __restrict__ ep2,
    const float* __restrict__ ep3, int ep_stride,
    const int* __restrict__ idx, int cnt)
{
    if ((EPI==5 || EPI==6) && row >= cnt) return;
    float v = acc + bias[col];
    if (EPI == 1) {
        v += ep2[col]*ep1[(size_t)row*N + col];
        v *= sigmoidf_(ep3[(size_t)row*ep_stride + col]);
        ((__half*)Cv)[(size_t)row*N + col] = __float2half_rn(v);
    } else if (EPI == 5) {
        v = 0.5f*v*(1.f + erff(v*0.70710678118654752f));
        ((__half*)Cv)[(size_t)row*N + col] = __float2half_rn(v);
    } else if (EPI == 6) {
        int gr = idx[row];
        ((float*)Cv)[(size_t)gr*N + col] += ep1[(size_t)gr*4]*v;
    } else {
        if (EPI == 2) v += ep1[(size_t)row*ep_stride + col];
        ((float*)Cv)[(size_t)row*N + col] = v;
        if (EPI == 2) ((float*)ep2)[(size_t)row*N + col] = v;   // dual store -> d_out
    }
}

template<int EPI>
__global__ void __launch_bounds__(256, 2) gemm_fp16(
    const __half* __restrict__ A, const __half* __restrict__ Bh,
    void* __restrict__ Cv, int M, int N, int K,
    const float* __restrict__ bias,
    const float* __restrict__ ep1, const float* __restrict__ ep2,
    const float* __restrict__ ep3, int ep_stride,
    const int* __restrict__ idx, const int* __restrict__ cnt_ptr)
{
    extern __shared__ char smem[];
    int tid = threadIdx.x, lane = tid & 31, warp = tid >> 5;
    int wm = (warp >> 2)*64, wn = (warp & 3)*32;   // warp tile 64x32
    int rowBase = blockIdx.y*128, colBase = blockIdx.x*128;

    int cnt = M;
    if (EPI==5 || EPI==6){
        cnt = *cnt_ptr;
        if (rowBase >= cnt) return;
    }

    // A fill: 128 rows x 64 halves; one row per 2 threads, 32 halves each
    int ar = tid >> 1;
    int acol = (tid & 1)*32;
    int arow_l = rowBase + ar;
    if (EPI==5 || EPI==6) arow_l = min(arow_l, cnt-1);
    int arow = (EPI==5) ? idx[arow_l] : arow_l;
    const __half* aSrc = A + (size_t)arow*K + acol;
    // B fill: 32 pair-rows x 256 halves; one row per 8 threads, 32 halves each
    int br = tid >> 3;
    int bcol = (tid & 7)*32;
    const __half* bSrc = Bh + (size_t)br*(2*N) + 2*colBase + bcol;

    unsigned asBase = (unsigned)__cvta_generic_to_shared(smem);
    unsigned bsBase = asBase + NSTAGE*A_STAGE_B;

    float acc[4][4][4];
    #pragma unroll
    for (int i=0;i<4;i++)
        #pragma unroll
        for (int j=0;j<4;j++)
            #pragma unroll
            for (int r=0;r<4;r++) acc[i][j][r]=0.f;

    int nk = K/KT;

    // prologue: stages 0,1
    #pragma unroll
    for (int s = 0; s < 2; s++){
        if (s < nk){
            unsigned ad = asBase + s*A_STAGE_B + (ar*AS_TH + acol)*2;
            const __half* as = aSrc + s*KT;
            cpa16(ad,    as);     cpa16(ad+16, as+8);
            cpa16(ad+32, as+16);  cpa16(ad+48, as+24);
            unsigned bd = bsBase + s*B_STAGE_B + br*(BS_TW*4) + bcol*2;
            const __half* bs = bSrc + (size_t)(s*32)*(2*N);
            cpa16(bd,    bs);     cpa16(bd+16, bs+8);
            cpa16(bd+32, bs+16);  cpa16(bd+48, bs+24);
            asm volatile("cp.async.commit_group;");
        }
    }

    for (int kt = 0; kt < nk; kt++){
        if (kt+2 < nk){
            int stg = (kt+2)%NSTAGE;
            unsigned ad = asBase + stg*A_STAGE_B + (ar*AS_TH + acol)*2;
            const __half* as = aSrc + (kt+2)*KT;
            cpa16(ad,    as);     cpa16(ad+16, as+8);
            cpa16(ad+32, as+16);  cpa16(ad+48, as+24);
            unsigned bd = bsBase + stg*B_STAGE_B + br*(BS_TW*4) + bcol*2;
            const __half* bs = bSrc + (size_t)((kt+2)*32)*(2*N);
            cpa16(bd,    bs);     cpa16(bd+16, bs+8);
            cpa16(bd+32, bs+16);  cpa16(bd+48, bs+24);
            asm volatile("cp.async.commit_group;");
            asm volatile("cp.async.wait_group 2;");
        } else if (kt+1 < nk){
            asm volatile("cp.async.wait_group 1;");
        } else {
            asm volatile("cp.async.wait_group 0;");
        }
        __syncthreads();

        int cur = kt % NSTAGE;
        const unsigned* AsW = (const unsigned*)(smem + cur*A_STAGE_B);
        const unsigned* BsW = (const unsigned*)(smem + NSTAGE*A_STAGE_B + cur*B_STAGE_B);

        #pragma unroll
        for (int kk = 0; kk < 32; kk += 8){          // pair units; 8 pairs = k16
            unsigned a[4][4], b[4][2];
            int cw = kk + (lane&3);
            #pragma unroll
            for (int i=0;i<4;i++){
                int r = wm + i*16 + (lane>>2);
                a[i][0] = AsW[r*AS_TW + cw];
                a[i][1] = AsW[(r+8)*AS_TW + cw];
                a[i][2] = AsW[r*AS_TW + cw + 4];
                a[i][3] = AsW[(r+8)*AS_TW + cw + 4];
            }
            #pragma unroll
            for (int j=0;j<4;j++){
                int cb = wn + j*8 + (lane>>2);
                b[j][0] = BsW[cw*BS_TW + cb];
                b[j][1] = BsW[(cw+4)*BS_TW + cb];
            }
            #pragma unroll
            for (int i=0;i<4;i++)
                #pragma unroll
                for (int j=0;j<4;j++){
                    asm volatile(
                        "mma.sync.aligned.m16n8k16.row.col.f32.f16.f16.f32 "
                        "{%0,%1,%2,%3}, {%4,%5,%6,%7}, {%8,%9}, {%0,%1,%2,%3};"
                        : "+f"(acc[i][j][0]), "+f"(acc[i][j][1]),
                          "+f"(acc[i][j][2]), "+f"(acc[i][j][3])
                        : "r"(a[i][0]), "r"(a[i][1]), "r"(a[i][2]), "r"(a[i][3]),
                          "r"(b[j][0]), "r"(b[j][1]));
                }
        }
        __syncthreads();
    }

    #pragma unroll
    for (int i=0;i<4;i++){
        #pragma unroll
        for (int j=0;j<4;j++){
            int r0 = rowBase + wm + i*16 + (lane>>2);
            int c0 = colBase + wn + j*8 + 2*(lane&3);
            epi_store<EPI>(Cv, r0,   c0,   N, acc[i][j][0], bias, ep1, ep2, ep3, ep_stride, idx, cnt);
            epi_store<EPI>(Cv, r0,   c0+1, N, acc[i][j][1], bias, ep1, ep2, ep3, ep_stride, idx, cnt);
            epi_store<EPI>(Cv, r0+8, c0,   N, acc[i][j][2], bias, ep1, ep2, ep3, ep_stride, idx, cnt);
            epi_store<EPI>(Cv, r0+8, c0+1, N, acc[i][j][3], bias, ep1, ep2, ep3, ep_stride, idx, cnt);
        }
    }
}

// ---------------- pack dt/B/C weights -> half2 interleaved [INNER/2][256] --
__global__ void pack_w_kernel(const float* __restrict__ dtw, const float* __restrict__ bpw,
                              const float* __restrict__ cpw, const float* __restrict__ dtb,
                              const float* __restrict__ bpb, const float* __restrict__ cpb,
                              __half2* __restrict__ W, float* __restrict__ bias)
{
    int i = blockIdx.x*blockDim.x + threadIdx.x;   // over (INNER/2)*256
    if (i >= (INNER/2)*256) return;
    int p = i >> 8, c = i & 255;
    float v0 = 0.f, v1 = 0.f;
    int k0 = 2*p, k1 = 2*p+1;
    if      (c < 64) { v0 = dtw[k0*64 + c];       v1 = dtw[k1*64 + c]; }
    else if (c < 128){ v0 = bpw[k0*64 + c - 64];  v1 = bpw[k1*64 + c - 64]; }
    else if (c < 192){ v0 = cpw[k0*64 + c - 128]; v1 = cpw[k1*64 + c - 128]; }
    W[i] = __floats2half2_rn(v0, v1);
    if (i < 256){
        float b = 0.f;
        if      (i < 64)  b = dtb[i];
        else if (i < 128) b = bpb[i-64];
        else if (i < 192) b = cpb[i-128];
        bias[i] = b;
    }
}

// ---------------- causal depthwise conv (K=3) + bias + silu ----------------
__global__ void conv_silu_kernel(const float* __restrict__ xz,
                                 const float* __restrict__ cw,
                                 const float* __restrict__ cb,
                                 float* __restrict__ xm, __half* __restrict__ xmh)
{
    int idx = blockIdx.x*blockDim.x + threadIdx.x;
    if (idx >= MM*INNER) return;
    int c  = idx & (INNER-1);
    int rt = idx >> 11;
    int t  = rt & (TT-1);
    const float* w = cw + c*3;
    float v = w[2]*xz[(size_t)rt*(2*INNER) + c];
    if (t >= 1) v += w[1]*xz[(size_t)(rt-1)*(2*INNER) + c];
    if (t >= 2) v += w[0]*xz[(size_t)(rt-2)*(2*INNER) + c];
    v += cb[c];
    float s = v * sigmoidf_(v);
    xm [(size_t)rt*INNER + c] = s;
    xmh[(size_t)rt*INNER + c] = __float2half_rn(s);
}

// ---------------- selective-scan over packed P [row,256] -------------------
__global__ void scan_kernel(const float* __restrict__ P, float* __restrict__ y)
{
    __shared__ float sA[256], sU[256];
    int bs = blockIdx.x;
    int b = bs >> 6, s = bs & 63;
    int tid = threadIdx.x;
    size_t baseP = (size_t)b*TT*256 + s;
    size_t baseY = (size_t)b*TT*DSTATE + s;
    float a_l[8], u_l[8], c_l[8];
    float A = 1.f, U = 0.f;
    #pragma unroll
    for (int i=0;i<8;i++){
        int t = tid*8 + i;
        size_t off = baseP + (size_t)t*256;
        float d  = sigmoidf_(P[off]);
        float bb = P[off + 64];
        c_l[i] = P[off + 128];
        float a = 1.f - d, u = d*bb;
        a_l[i]=a; u_l[i]=u;
        U = a*U + u;  A = a*A;
    }
    sA[tid]=A; sU[tid]=U; __syncthreads();
    for (int off=1; off<256; off<<=1){
        float pa=1.f, pu=0.f;
        if (tid >= off){ pa = sA[tid-off]; pu = sU[tid-off]; }
        __syncthreads();
        if (tid >= off){ U = A*pu + U; A = A*pa; }
        sA[tid]=A; sU[tid]=U; __syncthreads();
    }
    float state = (tid > 0) ? sU[tid-1] : 0.f;
    #pragma unroll
    for (int i=0;i<8;i++){
        state = a_l[i]*state + u_l[i];
        int t = tid*8 + i;
        y[baseY + (size_t)t*DSTATE] = c_l[i]*state;
    }
}

// ---------------- layernorm over dim 64 -> fp16 ----------------------------
__global__ void ln64_kernel(const float* __restrict__ y, __half* __restrict__ yh)
{
    __shared__ float red[64];
    __shared__ float mu_s, var_s;
    int row = blockIdx.x, tid = threadIdx.x;
    float v = y[(size_t)row*64 + tid];
    red[tid] = v; __syncthreads();
    for (int off=32; off>0; off>>=1){ if (tid<off) red[tid]+=red[tid+off]; __syncthreads(); }
    if (tid==0) mu_s = red[0]/64.f;
    __syncthreads();
    float d = v - mu_s;
    red[tid] = d*d; __syncthreads();
    for (int off=32; off>0; off>>=1){ if (tid<off) red[tid]+=red[tid+off]; __syncthreads(); }
    if (tid==0) var_s = red[0]/64.f;
    __syncthreads();
    yh[(size_t)row*64 + tid] = __float2half_rn(d * rsqrtf(var_s + 1e-5f));
}

// ---------------- deterministic per-expert row compaction ------------------
__global__ void compact_kernel(const float* __restrict__ wf, int* __restrict__ idxs,
                               int* __restrict__ cnts)
{
    __shared__ int sbuf[256];
    int e = blockIdx.x, tid = threadIdx.x;
    int base = 0;
    for (int chunk = 0; chunk < MM/256; chunk++){
        int row = chunk*256 + tid;
        int p = (wf[(size_t)row*4 + e] > 0.f) ? 1 : 0;
        sbuf[tid] = p; __syncthreads();
        for (int off=1; off<256; off<<=1){
            int v = (tid >= off) ? sbuf[tid-off] : 0;
            __syncthreads();
            sbuf[tid] += v;
            __syncthreads();
        }
        if (p) idxs[(size_t)e*MM + base + sbuf[tid] - 1] = row;
        base += sbuf[255];
        __syncthreads();
    }
    if (tid == 0) cnts[e] = base;
}

// ---------------- host launcher ----------------
static void* symv(const void* s){ void* p=nullptr; cudaGetSymbolAddress(&p, s); return p; }

extern "C" void kernel_launch(void* const* d_in, const int* in_sizes, int n_in,
                              void* d_out, int out_size)
{
    const float* x        = (const float*)d_in[0];
    const float* norm1_w  = (const float*)d_in[1];
    const float* norm2_w  = (const float*)d_in[2];
    const float* in_proj_w= (const float*)d_in[3];
    const float* in_proj_b= (const float*)d_in[4];
    const float* conv_w   = (const float*)d_in[5];
    const float* conv_b   = (const float*)d_in[6];
    const float* dt_w     = (const float*)d_in[7];
    const float* dt_b     = (const float*)d_in[8];
    const float* bp_w     = (const float*)d_in[9];
    const float* bp_b     = (const float*)d_in[10];
    const float* cp_w     = (const float*)d_in[11];
    const float* cp_b     = (const float*)d_in[12];
    const float* s2i_w    = (const float*)d_in[13];
    const float* s2i_b    = (const float*)d_in[14];
    const float* D_param  = (const float*)d_in[15];
    const float* out_w    = (const float*)d_in[16];
    const float* out_b    = (const float*)d_in[17];
    const float* gate_w   = (const float*)d_in[18];
    const float* gate_b   = (const float*)d_in[19];
    const float* e_w1     = (const float*)d_in[20];
    const float* e_b1     = (const float*)d_in[21];
    const float* e_w2     = (const float*)d_in[22];
    const float* e_b2     = (const float*)d_in[23];
    float* out = (float*)d_out;

    __half*  p_hh  = (__half*)symv(g_hh);
    float*   p_xz  = (float*)symv(g_xz);
    float*   p_xm  = (float*)symv(g_xm);
    __half*  p_xmh = (__half*)symv(g_xmh);
    float*   p_P   = (float*)symv(g_P);
    float*   p_y   = (float*)symv(g_y);
    __half*  p_yh  = (__half*)symv(g_yh);
    __half*  p_y2h = (__half*)symv(g_y2h);
    float*   p_x1  = (float*)symv(g_x1);
    __half*  p_h2h = (__half*)symv(g_h2h);
    float*   p_wf  = (float*)symv(g_wf);
    __half*  p_hid = (__half*)symv(g_hid);
    __half2* p_wWp = (__half2*)symv(g_wWp);
    float*   p_bp  = (float*)symv(g_bp);
    __half2* p_wIn = (__half2*)symv(g_wIn);
    __half2* p_wS2i= (__half2*)symv(g_wS2i);
    __half2* p_wOut= (__half2*)symv(g_wOut);
    __half2* p_wE1 = (__half2*)symv(g_wE1);
    __half2* p_wE2 = (__half2*)symv(g_wE2);
    int*     p_idx = (int*)symv(g_idx);
    int*     p_cnt = (int*)symv(g_cnt);

    cudaFuncSetAttribute(gemm_fp16<0>, cudaFuncAttributeMaxDynamicSharedMemorySize, SMEM_BYTES);
    cudaFuncSetAttribute(gemm_fp16<1>, cudaFuncAttributeMaxDynamicSharedMemorySize, SMEM_BYTES);
    cudaFuncSetAttribute(gemm_fp16<2>, cudaFuncAttributeMaxDynamicSharedMemorySize, SMEM_BYTES);
    cudaFuncSetAttribute(gemm_fp16<5>, cudaFuncAttributeMaxDynamicSharedMemorySize, SMEM_BYTES);
    cudaFuncSetAttribute(gemm_fp16<6>, cudaFuncAttributeMaxDynamicSharedMemorySize, SMEM_BYTES);

    // 0. weight prep: pack dt/B/C; convert all GEMM B weights to fp16 pairs
    pack_w_kernel<<<((INNER/2)*256 + 255)/256, 256>>>(dt_w, bp_w, cp_w, dt_b, bp_b, cp_b, p_wWp, p_bp);
    cvtw_kernel<<<((DD/2)*(2*INNER) + 255)/256, 256>>>(in_proj_w, p_wIn, (DD/2)*(2*INNER), 2*INNER);
    cvtw_kernel<<<((DSTATE/2)*INNER + 255)/256, 256>>>(s2i_w, p_wS2i, (DSTATE/2)*INNER, INNER);
    cvtw_kernel<<<((INNER/2)*DD + 255)/256, 256>>>(out_w, p_wOut, (INNER/2)*DD, DD);
    cvtw_kernel<<<((EE*DD/2)*HID + 255)/256, 256>>>(e_w1, p_wE1, (EE*DD/2)*HID, HID);
    cvtw_kernel<<<((EE*HID/2)*DD + 255)/256, 256>>>(e_w2, p_wE2, (EE*HID/2)*DD, DD);

    // 1. rmsnorm(x) -> h (fp16)
    rmsnorm_kernel<<<MM, 256>>>(x, norm1_w, p_hh);

    // 2. xz = h @ in_proj_w + b  [4096,4096] K=1024
    gemm_fp16<0><<<dim3(2*INNER/128, MM/128), 256, SMEM_BYTES>>>(p_hh, (const __half*)p_wIn, p_xz,
        MM, 2*INNER, DD, in_proj_b, nullptr, nullptr, nullptr, 0, nullptr, nullptr);

    // 3. conv + silu -> x_main (exact + fp16)
    conv_silu_kernel<<<(MM*INNER)/256, 256>>>(p_xz, conv_w, conv_b, p_xm, p_xmh);

    // 4. P = xmh @ Wp + bp  [4096,256] K=2048
    gemm_fp16<0><<<dim3(256/128, MM/128), 256, SMEM_BYTES>>>(p_xmh, (const __half*)p_wWp, p_P,
        MM, 256, INNER, p_bp, nullptr, nullptr, nullptr, 0, nullptr, nullptr);

    // 5. selective scan -> y (float)
    scan_kernel<<<BB*DSTATE, 256>>>(p_P, p_y);

    // 6. layernorm over 64 -> yh (fp16)
    ln64_kernel<<<MM, 64>>>(p_y, p_yh);

    // 7. y2 = (y @ s2i_w + b + D*xm) * sigmoid(gate) -> fp16  K=64
    gemm_fp16<1><<<dim3(INNER/128, MM/128), 256, SMEM_BYTES>>>(p_yh, (const __half*)p_wS2i, p_y2h,
        MM, INNER, DSTATE, s2i_b, p_xm, D_param, p_xz + INNER, 2*INNER, nullptr, nullptr);

    // 8. x1 = x + (y2 @ out_w + b), dual-stored to x1 AND d_out  K=2048
    gemm_fp16<2><<<dim3(DD/128, MM/128), 256, SMEM_BYTES>>>(p_y2h, (const __half*)p_wOut, p_x1,
        MM, DD, INNER, out_b, x, out, nullptr, DD, nullptr, nullptr);

    // 9. rmsnorm2 + gating fused -> h2h (fp16), wf
    rms2_gate_kernel<<<MM, 256>>>(p_x1, norm2_w, gate_w, gate_b, p_h2h, p_wf);

    // 10. compaction -> idx/cnt
    compact_kernel<<<EE, 256>>>(p_wf, p_idx, p_cnt);

    // 11. per-expert compacted MoE (accumulates into d_out)
    for (int e = 0; e < EE; e++){
        gemm_fp16<5><<<dim3(HID/128, MM/128), 256, SMEM_BYTES>>>(p_h2h,
            (const __half*)(p_wE1 + (size_t)e*(DD/2)*HID), p_hid,
            MM, HID, DD, e_b1 + (size_t)e*HID, nullptr, nullptr, nullptr, 0,
            p_idx + (size_t)e*MM, p_cnt + e);
        gemm_fp16<6><<<dim3(DD/128, MM/128), 256, SMEM_BYTES>>>(p_hid,
            (const __half*)(p_wE2 + (size_t)e*(HID/2)*DD), out,
            MM, DD, HID, e_b2 + (size_t)e*DD, p_wf + e, nullptr, nullptr, 0,
            p_idx + (size_t)e*MM, p_cnt + e);
    }
}

// round 15
// speedup vs baseline: 2.2348x; 1.1984x over previous
#include <cuda_runtime.h>
#include <cuda_fp16.h>
#include <math.h>

// ---------------- problem constants ----------------
#define BB 2
#define TT 2048
#define DD 1024
#define MM (BB*TT)          // 4096 token rows
#define INNER 2048
#define DSTATE 64
#define EE 4
#define HID 4096

// ---------------- scratch (device globals; no allocation allowed) ----------
__device__ __half g_hh  [MM*DD];        // rmsnorm1 output (fp16)
__device__ float  g_xz  [MM*2*INNER];   // exact
__device__ float  g_xm  [MM*INNER];     // exact (epilogue use)
__device__ __half g_xmh [MM*INNER];     // fp16 (GEMM A)
__device__ float  g_P   [MM*256];       // packed dt|B|C projections (exact)
__device__ float  g_y   [MM*DSTATE];    // scan output (float)
__device__ __half g_yh  [MM*DSTATE];    // ln64 output (fp16)
__device__ __half g_y2h [MM*INNER];     // fp16
__device__ float  g_x1  [MM*DD];        // exact
__device__ __half g_h2h [MM*DD];        // fp16 (GEMM A)
__device__ float  g_wf  [MM*EE];
__device__ __half g_hid [(size_t)EE*MM*HID];   // per-expert fp16 hidden
__device__ float  g_eo  [(size_t)EE*MM*DD];    // per-expert dense expert outputs
__device__ int    g_idx [EE*MM];
__device__ int    g_cnt [EE];
// fp16 k-pair-interleaved weights: word[p*N+n] = {W[2p][n], W[2p+1][n]}
__device__ __half2 g_wWp [(INNER/2)*256];
__device__ float   g_bp  [256];
__device__ __half2 g_wIn [(DD/2)*(2*INNER)];
__device__ __half2 g_wS2i[(DSTATE/2)*INNER];
__device__ __half2 g_wOut[(INNER/2)*DD];
__device__ __half2 g_wE1 [(size_t)(EE*DD/2)*HID];
__device__ __half2 g_wE2 [(size_t)(EE*HID/2)*DD];

// ---------------- helpers ----------------
__device__ __forceinline__ float sigmoidf_(float x){ return 1.f/(1.f+expf(-x)); }
__device__ __forceinline__ void cpa16(unsigned dst, const void* src){
    asm volatile("cp.async.cg.shared.global [%0], [%1], 16;" :: "r"(dst), "l"(src));
}

// ---------------- weight conversion: f32 [K][N] -> half2 interleaved (x4) --
__global__ void cvtw_kernel(const float* __restrict__ W, __half2* __restrict__ out,
                            int nwords, int N)
{
    int i4 = (blockIdx.x*blockDim.x + threadIdx.x)*4;
    if (i4 >= nwords) return;
    int p = i4 / N, n = i4 - p*N;
    float4 a = *reinterpret_cast<const float4*>(&W[(size_t)(2*p)*N + n]);
    float4 b = *reinterpret_cast<const float4*>(&W[(size_t)(2*p+1)*N + n]);
    __half2 h[4];
    h[0] = __floats2half2_rn(a.x, b.x);
    h[1] = __floats2half2_rn(a.y, b.y);
    h[2] = __floats2half2_rn(a.z, b.z);
    h[3] = __floats2half2_rn(a.w, b.w);
    *reinterpret_cast<uint4*>(&out[i4]) = *reinterpret_cast<uint4*>(h);
}

// ---------------- rmsnorm (norm1): fp16 output ----------------
__global__ void rmsnorm_kernel(const float* __restrict__ x, const float* __restrict__ w,
                               __half* __restrict__ out_h)
{
    __shared__ float red[256];
    int row = blockIdx.x, tid = threadIdx.x;
    const float* xr = x + (size_t)row*DD;
    float s = 0.f;
    #pragma unroll
    for (int i = 0; i < DD/256; i++){ float v = xr[tid + i*256]; s += v*v; }
    red[tid] = s; __syncthreads();
    for (int off = 128; off > 0; off >>= 1){ if (tid < off) red[tid] += red[tid+off]; __syncthreads(); }
    float nr = rsqrtf(red[0]/(float)DD + 1e-6f);
    #pragma unroll
    for (int i = 0; i < DD/256; i++){
        int c = tid + i*256;
        out_h[(size_t)row*DD + c] = __float2half_rn(xr[c]*nr*w[c]);
    }
}

// ---------------- rmsnorm2 + gating fused (fp16 h2 + wf) -------------------
__global__ void rms2_gate_kernel(const float* __restrict__ x1, const float* __restrict__ w,
                                 const float* __restrict__ gw, const float* __restrict__ gb,
                                 __half* __restrict__ h2h, float* __restrict__ wf)
{
    __shared__ float red[256];
    __shared__ float4 red4[256];
    int row = blockIdx.x, tid = threadIdx.x;
    const float* xr = x1 + (size_t)row*DD;
    float s = 0.f;
    #pragma unroll
    for (int i = 0; i < DD/256; i++){ float v = xr[tid + i*256]; s += v*v; }
    red[tid] = s; __syncthreads();
    for (int off = 128; off > 0; off >>= 1){ if (tid < off) red[tid] += red[tid+off]; __syncthreads(); }
    float nr = rsqrtf(red[0]/(float)DD + 1e-6f);
    float p0=0.f,p1=0.f,p2=0.f,p3=0.f;
    #pragma unroll
    for (int i = 0; i < DD/256; i++){
        int c = tid + i*256;
        float v = xr[c]*nr*w[c];
        h2h[(size_t)row*DD + c] = __float2half_rn(v);
        const float* g = gw + c*4;
        p0 = fmaf(v, g[0], p0); p1 = fmaf(v, g[1], p1);
        p2 = fmaf(v, g[2], p2); p3 = fmaf(v, g[3], p3);
    }
    red4[tid] = make_float4(p0,p1,p2,p3); __syncthreads();
    for (int off = 128; off > 0; off >>= 1){
        if (tid < off){
            float4 a = red4[tid], b = red4[tid+off];
            red4[tid] = make_float4(a.x+b.x, a.y+b.y, a.z+b.z, a.w+b.w);
        }
        __syncthreads();
    }
    if (tid == 0){
        float l[4] = {red4[0].x+gb[0], red4[0].y+gb[1], red4[0].z+gb[2], red4[0].w+gb[3]};
        int i0 = 0;
        #pragma unroll
        for (int e=1;e<4;e++) if (l[e] > l[i0]) i0 = e;
        int i1 = -1;
        #pragma unroll
        for (int e=0;e<4;e++) if (e != i0 && (i1 < 0 || l[e] > l[i1])) i1 = e;
        float ex = expf(l[i1] - l[i0]);
        float q0 = 1.f/(1.f+ex), q1 = ex/(1.f+ex);
        float wv[4] = {0.f,0.f,0.f,0.f};
        wv[i0]=q0; wv[i1]=q1;
        #pragma unroll
        for (int e=0;e<4;e++) wf[(size_t)row*4+e]=wv[e];
    }
}

// ======= FP16 GEMM (m16n8k16), cp.async 3-stage, 128x128x64, 2 CTA/SM ======
// EPI: 0 bias->f32 | 2 residual->f32
//      5 gathered-A gelu->f16 (z = expert) | 6 scatter-store->f32 (z = expert)
#define KT 64                 // k-tile (halves)
#define AS_TH 72              // A row stride (halves)
#define AS_TW 36              // A row stride (words)
#define BS_TW 136             // B pair-row stride (words)
#define A_STAGE_B (128*AS_TH*2)   // 18432 B
#define B_STAGE_B (32*BS_TW*4)    // 17408 B
#define NSTAGE 3
#define SMEM_BYTES (NSTAGE*(A_STAGE_B + B_STAGE_B))   // 107520 B

template<int EPI>
__device__ __forceinline__ void epi_store(
    void* __restrict__ Cv, int row, int col, int N, float acc,
    const float* __restrict__ bias,
    const float* __restrict__ ep1, int ep_stride,
    const int* __restrict__ idx, int cnt)
{
    if ((EPI==5 || EPI==6) && row >= cnt) return;
    float v = acc + bias[col];
    if (EPI == 5) {
        v = 0.5f*v*(1.f + erff(v*0.70710678118654752f));
        ((__half*)Cv)[(size_t)row*N + col] = __float2half_rn(v);
    } else if (EPI == 6) {
        ((float*)Cv)[(size_t)idx[row]*N + col] = v;
    } else if (EPI == 2) {
        v += ep1[(size_t)row*ep_stride + col];
        ((float*)Cv)[(size_t)row*N + col] = v;
    } else {
        ((float*)Cv)[(size_t)row*N + col] = v;
    }
}

// s2i epilogue: (acc + bias + D*xm) * sigmoid(gate) -> fp16
__device__ __forceinline__ void epi_store1(
    __half* __restrict__ C, int row, int col, int N, float acc,
    const float* __restrict__ bias,
    const float* __restrict__ xm, const float* __restrict__ Dp,
    const float* __restrict__ gate, int ep_stride)
{
    float v = acc + bias[col];
    v += Dp[col]*xm[(size_t)row*N + col];
    v *= sigmoidf_(gate[(size_t)row*ep_stride + col]);
    C[(size_t)row*N + col] = __float2half_rn(v);
}

template<int EPI>
__global__ void __launch_bounds__(256, 2) gemm_fp16(
    const __half* __restrict__ A, const __half* __restrict__ Bh,
    void* __restrict__ Cv, int M, int N, int K,
    const float* __restrict__ bias, int biasStride,
    const float* __restrict__ ep1, int ep_stride,
    const int* __restrict__ idx, const int* __restrict__ cnt_ptr,
    long long azStride, long long bzStride, long long czStrideBytes)
{
    extern __shared__ char smem[];
    int tid = threadIdx.x, lane = tid & 31, warp = tid >> 5;
    int wm = (warp >> 2)*64, wn = (warp & 3)*32;   // warp tile 64x32
    int rowBase = blockIdx.y*128, colBase = blockIdx.x*128;
    int ez = blockIdx.z;

    const __half* Az = A + (size_t)ez*azStride;
    const __half* Bz = Bh + (size_t)ez*bzStride;
    void* Cz = (char*)Cv + (size_t)ez*czStrideBytes;
    const float* biasz = bias + (size_t)ez*biasStride;
    const int* idxz = idx;

    int cnt = M;
    if (EPI==5 || EPI==6){
        cnt = cnt_ptr[ez];
        idxz = idx + (size_t)ez*MM;
        if (rowBase >= cnt) return;
    }

    // A fill: 128 rows x 64 halves; one row per 2 threads, 32 halves each
    int ar = tid >> 1;
    int acol = (tid & 1)*32;
    int arow_l = rowBase + ar;
    if (EPI==5 || EPI==6) arow_l = min(arow_l, cnt-1);
    int arow = (EPI==5) ? idxz[arow_l] : arow_l;
    const __half* aSrc = Az + (size_t)arow*K + acol;
    // B fill: 32 pair-rows x 256 halves; one row per 8 threads, 32 halves each
    int br = tid >> 3;
    int bcol = (tid & 7)*32;
    const __half* bSrc = Bz + (size_t)br*(2*N) + 2*colBase + bcol;

    unsigned asBase = (unsigned)__cvta_generic_to_shared(smem);
    unsigned bsBase = asBase + NSTAGE*A_STAGE_B;

    float acc[4][4][4];
    #pragma unroll
    for (int i=0;i<4;i++)
        #pragma unroll
        for (int j=0;j<4;j++)
            #pragma unroll
            for (int r=0;r<4;r++) acc[i][j][r]=0.f;

    int nk = K/KT;

    // prologue: stages 0,1
    #pragma unroll
    for (int s = 0; s < 2; s++){
        if (s < nk){
            unsigned ad = asBase + s*A_STAGE_B + (ar*AS_TH + acol)*2;
            const __half* as = aSrc + s*KT;
            cpa16(ad,    as);     cpa16(ad+16, as+8);
            cpa16(ad+32, as+16);  cpa16(ad+48, as+24);
            unsigned bd = bsBase + s*B_STAGE_B + br*(BS_TW*4) + bcol*2;
            const __half* bs = bSrc + (size_t)(s*32)*(2*N);
            cpa16(bd,    bs);     cpa16(bd+16, bs+8);
            cpa16(bd+32, bs+16);  cpa16(bd+48, bs+24);
            asm volatile("cp.async.commit_group;");
        }
    }

    for (int kt = 0; kt < nk; kt++){
        if (kt+2 < nk){
            int stg = (kt+2)%NSTAGE;
            unsigned ad = asBase + stg*A_STAGE_B + (ar*AS_TH + acol)*2;
            const __half* as = aSrc + (kt+2)*KT;
            cpa16(ad,    as);     cpa16(ad+16, as+8);
            cpa16(ad+32, as+16);  cpa16(ad+48, as+24);
            unsigned bd = bsBase + stg*B_STAGE_B + br*(BS_TW*4) + bcol*2;
            const __half* bs = bSrc + (size_t)((kt+2)*32)*(2*N);
            cpa16(bd,    bs);     cpa16(bd+16, bs+8);
            cpa16(bd+32, bs+16);  cpa16(bd+48, bs+24);
            asm volatile("cp.async.commit_group;");
            asm volatile("cp.async.wait_group 2;");
        } else if (kt+1 < nk){
            asm volatile("cp.async.wait_group 1;");
        } else {
            asm volatile("cp.async.wait_group 0;");
        }
        __syncthreads();

        int cur = kt % NSTAGE;
        const unsigned* AsW = (const unsigned*)(smem + cur*A_STAGE_B);
        const unsigned* BsW = (const unsigned*)(smem + NSTAGE*A_STAGE_B + cur*B_STAGE_B);

        #pragma unroll
        for (int kk = 0; kk < 32; kk += 8){          // pair units; 8 pairs = k16
            unsigned a[4][4], b[4][2];
            int cw = kk + (lane&3);
            #pragma unroll
            for (int i=0;i<4;i++){
                int r = wm + i*16 + (lane>>2);
                a[i][0] = AsW[r*AS_TW + cw];
                a[i][1] = AsW[(r+8)*AS_TW + cw];
                a[i][2] = AsW[r*AS_TW + cw + 4];
                a[i][3] = AsW[(r+8)*AS_TW + cw + 4];
            }
            #pragma unroll
            for (int j=0;j<4;j++){
                int cb = wn + j*8 + (lane>>2);
                b[j][0] = BsW[cw*BS_TW + cb];
                b[j][1] = BsW[(cw+4)*BS_TW + cb];
            }
            #pragma unroll
            for (int i=0;i<4;i++)
                #pragma unroll
                for (int j=0;j<4;j++){
                    asm volatile(
                        "mma.sync.aligned.m16n8k16.row.col.f32.f16.f16.f32 "
                        "{%0,%1,%2,%3}, {%4,%5,%6,%7}, {%8,%9}, {%0,%1,%2,%3};"
                        : "+f"(acc[i][j][0]), "+f"(acc[i][j][1]),
                          "+f"(acc[i][j][2]), "+f"(acc[i][j][3])
                        : "r"(a[i][0]), "r"(a[i][1]), "r"(a[i][2]), "r"(a[i][3]),
                          "r"(b[j][0]), "r"(b[j][1]));
                }
        }
        __syncthreads();
    }

    #pragma unroll
    for (int i=0;i<4;i++){
        #pragma unroll
        for (int j=0;j<4;j++){
            int r0 = rowBase + wm + i*16 + (lane>>2);
            int c0 = colBase + wn + j*8 + 2*(lane&3);
            epi_store<EPI>(Cz, r0,   c0,   N, acc[i][j][0], biasz, ep1, ep_stride, idxz, cnt);
            epi_store<EPI>(Cz, r0,   c0+1, N, acc[i][j][1], biasz, ep1, ep_stride, idxz, cnt);
            epi_store<EPI>(Cz, r0+8, c0,   N, acc[i][j][2], biasz, ep1, ep_stride, idxz, cnt);
            epi_store<EPI>(Cz, r0+8, c0+1, N, acc[i][j][3], biasz, ep1, ep_stride, idxz, cnt);
        }
    }
}

// Specialized s2i-gate GEMM: separate kernel (3 epilogue tensors)
__global__ void __launch_bounds__(256, 2) gemm_fp16_s2i(
    const __half* __restrict__ A, const __half* __restrict__ Bh,
    __half* __restrict__ C, int M, int N, int K,
    const float* __restrict__ bias,
    const float* __restrict__ xm, const float* __restrict__ Dp,
    const float* __restrict__ gate, int ep_stride)
{
    extern __shared__ char smem[];
    int tid = threadIdx.x, lane = tid & 31, warp = tid >> 5;
    int wm = (warp >> 2)*64, wn = (warp & 3)*32;
    int rowBase = blockIdx.y*128, colBase = blockIdx.x*128;

    int ar = tid >> 1;
    int acol = (tid & 1)*32;
    const __half* aSrc = A + (size_t)(rowBase + ar)*K + acol;
    int br = tid >> 3;
    int bcol = (tid & 7)*32;
    const __half* bSrc = Bh + (size_t)br*(2*N) + 2*colBase + bcol;

    unsigned asBase = (unsigned)__cvta_generic_to_shared(smem);
    unsigned bsBase = asBase + NSTAGE*A_STAGE_B;

    float acc[4][4][4];
    #pragma unroll
    for (int i=0;i<4;i++)
        #pragma unroll
        for (int j=0;j<4;j++)
            #pragma unroll
            for (int r=0;r<4;r++) acc[i][j][r]=0.f;

    int nk = K/KT;   // K=64 -> 1 tile
    #pragma unroll
    for (int s = 0; s < 2; s++){
        if (s < nk){
            unsigned ad = asBase + s*A_STAGE_B + (ar*AS_TH + acol)*2;
            const __half* as = aSrc + s*KT;
            cpa16(ad,    as);     cpa16(ad+16, as+8);
            cpa16(ad+32, as+16);  cpa16(ad+48, as+24);
            unsigned bd = bsBase + s*B_STAGE_B + br*(BS_TW*4) + bcol*2;
            const __half* bs = bSrc + (size_t)(s*32)*(2*N);
            cpa16(bd,    bs);     cpa16(bd+16, bs+8);
            cpa16(bd+32, bs+16);  cpa16(bd+48, bs+24);
            asm volatile("cp.async.commit_group;");
        }
    }
    for (int kt = 0; kt < nk; kt++){
        if (kt+1 < nk){ asm volatile("cp.async.wait_group 1;"); }
        else          { asm volatile("cp.async.wait_group 0;"); }
        __syncthreads();
        int cur = kt % NSTAGE;
        const unsigned* AsW = (const unsigned*)(smem + cur*A_STAGE_B);
        const unsigned* BsW = (const unsigned*)(smem + NSTAGE*A_STAGE_B + cur*B_STAGE_B);
        #pragma unroll
        for (int kk = 0; kk < 32; kk += 8){
            unsigned a[4][4], b[4][2];
            int cw = kk + (lane&3);
            #pragma unroll
            for (int i=0;i<4;i++){
                int r = wm + i*16 + (lane>>2);
                a[i][0] = AsW[r*AS_TW + cw];
                a[i][1] = AsW[(r+8)*AS_TW + cw];
                a[i][2] = AsW[r*AS_TW + cw + 4];
                a[i][3] = AsW[(r+8)*AS_TW + cw + 4];
            }
            #pragma unroll
            for (int j=0;j<4;j++){
                int cb = wn + j*8 + (lane>>2);
                b[j][0] = BsW[cw*BS_TW + cb];
                b[j][1] = BsW[(cw+4)*BS_TW + cb];
            }
            #pragma unroll
            for (int i=0;i<4;i++)
                #pragma unroll
                for (int j=0;j<4;j++){
                    asm volatile(
                        "mma.sync.aligned.m16n8k16.row.col.f32.f16.f16.f32 "
                        "{%0,%1,%2,%3}, {%4,%5,%6,%7}, {%8,%9}, {%0,%1,%2,%3};"
                        : "+f"(acc[i][j][0]), "+f"(acc[i][j][1]),
                          "+f"(acc[i][j][2]), "+f"(acc[i][j][3])
                        : "r"(a[i][0]), "r"(a[i][1]), "r"(a[i][2]), "r"(a[i][3]),
                          "r"(b[j][0]), "r"(b[j][1]));
                }
        }
        __syncthreads();
    }
    #pragma unroll
    for (int i=0;i<4;i++){
        #pragma unroll
        for (int j=0;j<4;j++){
            int r0 = rowBase + wm + i*16 + (lane>>2);
            int c0 = colBase + wn + j*8 + 2*(lane&3);
            epi_store1(C, r0,   c0,   N, acc[i][j][0], bias, xm, Dp, gate, ep_stride);
            epi_store1(C, r0,   c0+1, N, acc[i][j][1], bias, xm, Dp, gate, ep_stride);
            epi_store1(C, r0+8, c0,   N, acc[i][j][2], bias, xm, Dp, gate, ep_stride);
            epi_store1(C, r0+8, c0+1, N, acc[i][j][3], bias, xm, Dp, gate, ep_stride);
        }
    }
}

// ---------------- pack dt/B/C weights -> half2 interleaved [INNER/2][256] --
__global__ void pack_w_kernel(const float* __restrict__ dtw, const float* __restrict__ bpw,
                              const float* __restrict__ cpw, const float* __restrict__ dtb,
                              const float* __restrict__ bpb, const float* __restrict__ cpb,
                              __half2* __restrict__ W, float* __restrict__ bias)
{
    int i = blockIdx.x*blockDim.x + threadIdx.x;
    if (i >= (INNER/2)*256) return;
    int p = i >> 8, c = i & 255;
    float v0 = 0.f, v1 = 0.f;
    int k0 = 2*p, k1 = 2*p+1;
    if      (c < 64) { v0 = dtw[k0*64 + c];       v1 = dtw[k1*64 + c]; }
    else if (c < 128){ v0 = bpw[k0*64 + c - 64];  v1 = bpw[k1*64 + c - 64]; }
    else if (c < 192){ v0 = cpw[k0*64 + c - 128]; v1 = cpw[k1*64 + c - 128]; }
    W[i] = __floats2half2_rn(v0, v1);
    if (i < 256){
        float b = 0.f;
        if      (i < 64)  b = dtb[i];
        else if (i < 128) b = bpb[i-64];
        else if (i < 192) b = cpb[i-128];
        bias[i] = b;
    }
}

// ---------------- causal depthwise conv (K=3) + bias + silu ----------------
__global__ void conv_silu_kernel(const float* __restrict__ xz,
                                 const float* __restrict__ cw,
                                 const float* __restrict__ cb,
                                 float* __restrict__ xm, __half* __restrict__ xmh)
{
    int idx = blockIdx.x*blockDim.x + threadIdx.x;
    if (idx >= MM*INNER) return;
    int c  = idx & (INNER-1);
    int rt = idx >> 11;
    int t  = rt & (TT-1);
    const float* w = cw + c*3;
    float v = w[2]*xz[(size_t)rt*(2*INNER) + c];
    if (t >= 1) v += w[1]*xz[(size_t)(rt-1)*(2*INNER) + c];
    if (t >= 2) v += w[0]*xz[(size_t)(rt-2)*(2*INNER) + c];
    v += cb[c];
    float s = v * sigmoidf_(v);
    xm [(size_t)rt*INNER + c] = s;
    xmh[(size_t)rt*INNER + c] = __float2half_rn(s);
}

// ---------------- selective-scan over packed P [row,256] -------------------
__global__ void scan_kernel(const float* __restrict__ P, float* __restrict__ y)
{
    __shared__ float sA[256], sU[256];
    int bs = blockIdx.x;
    int b = bs >> 6, s = bs & 63;
    int tid = threadIdx.x;
    size_t baseP = (size_t)b*TT*256 + s;
    size_t baseY = (size_t)b*TT*DSTATE + s;
    float a_l[8], u_l[8], c_l[8];
    float A = 1.f, U = 0.f;
    #pragma unroll
    for (int i=0;i<8;i++){
        int t = tid*8 + i;
        size_t off = baseP + (size_t)t*256;
        float d  = sigmoidf_(P[off]);
        float bb = P[off + 64];
        c_l[i] = P[off + 128];
        float a = 1.f - d, u = d*bb;
        a_l[i]=a; u_l[i]=u;
        U = a*U + u;  A = a*A;
    }
    sA[tid]=A; sU[tid]=U; __syncthreads();
    for (int off=1; off<256; off<<=1){
        float pa=1.f, pu=0.f;
        if (tid >= off){ pa = sA[tid-off]; pu = sU[tid-off]; }
        __syncthreads();
        if (tid >= off){ U = A*pu + U; A = A*pa; }
        sA[tid]=A; sU[tid]=U; __syncthreads();
    }
    float state = (tid > 0) ? sU[tid-1] : 0.f;
    #pragma unroll
    for (int i=0;i<8;i++){
        state = a_l[i]*state + u_l[i];
        int t = tid*8 + i;
        y[baseY + (size_t)t*DSTATE] = c_l[i]*state;
    }
}

// ---------------- layernorm over dim 64 -> fp16 ----------------------------
__global__ void ln64_kernel(const float* __restrict__ y, __half* __restrict__ yh)
{
    __shared__ float red[64];
    __shared__ float mu_s, var_s;
    int row = blockIdx.x, tid = threadIdx.x;
    float v = y[(size_t)row*64 + tid];
    red[tid] = v; __syncthreads();
    for (int off=32; off>0; off>>=1){ if (tid<off) red[tid]+=red[tid+off]; __syncthreads(); }
    if (tid==0) mu_s = red[0]/64.f;
    __syncthreads();
    float d = v - mu_s;
    red[tid] = d*d; __syncthreads();
    for (int off=32; off>0; off>>=1){ if (tid<off) red[tid]+=red[tid+off]; __syncthreads(); }
    if (tid==0) var_s = red[0]/64.f;
    __syncthreads();
    yh[(size_t)row*64 + tid] = __float2half_rn(d * rsqrtf(var_s + 1e-5f));
}

// ---------------- deterministic per-expert row compaction ------------------
__global__ void compact_kernel(const float* __restrict__ wf, int* __restrict__ idxs,
                               int* __restrict__ cnts)
{
    __shared__ int sbuf[256];
    int e = blockIdx.x, tid = threadIdx.x;
    int base = 0;
    for (int chunk = 0; chunk < MM/256; chunk++){
        int row = chunk*256 + tid;
        int p = (wf[(size_t)row*4 + e] > 0.f) ? 1 : 0;
        sbuf[tid] = p; __syncthreads();
        for (int off=1; off<256; off<<=1){
            int v = (tid >= off) ? sbuf[tid-off] : 0;
            __syncthreads();
            sbuf[tid] += v;
            __syncthreads();
        }
        if (p) idxs[(size_t)e*MM + base + sbuf[tid] - 1] = row;
        base += sbuf[255];
        __syncthreads();
    }
    if (tid == 0) cnts[e] = base;
}

// ---------------- combine: out = x1 + sum_e wf[e]*eo_e ---------------------
__global__ void combine_kernel(const float* __restrict__ x1, const float* __restrict__ wf,
                               const float* __restrict__ eo, float* __restrict__ out)
{
    int row = blockIdx.x, tid = threadIdx.x;
    float w0 = wf[(size_t)row*4+0], w1 = wf[(size_t)row*4+1];
    float w2 = wf[(size_t)row*4+2], w3 = wf[(size_t)row*4+3];
    #pragma unroll
    for (int i = 0; i < DD/256; i++){
        int c = tid + i*256;
        size_t off = (size_t)row*DD + c;
        float o = x1[off];
        if (w0 > 0.f) o += w0*eo[off];
        if (w1 > 0.f) o += w1*eo[(size_t)MM*DD + off];
        if (w2 > 0.f) o += w2*eo[2*(size_t)MM*DD + off];
        if (w3 > 0.f) o += w3*eo[3*(size_t)MM*DD + off];
        out[off] = o;
    }
}

// ---------------- host launcher ----------------
static void* symv(const void* s){ void* p=nullptr; cudaGetSymbolAddress(&p, s); return p; }

extern "C" void kernel_launch(void* const* d_in, const int* in_sizes, int n_in,
                              void* d_out, int out_size)
{
    const float* x        = (const float*)d_in[0];
    const float* norm1_w  = (const float*)d_in[1];
    const float* norm2_w  = (const float*)d_in[2];
    const float* in_proj_w= (const float*)d_in[3];
    const float* in_proj_b= (const float*)d_in[4];
    const float* conv_w   = (const float*)d_in[5];
    const float* conv_b   = (const float*)d_in[6];
    const float* dt_w     = (const float*)d_in[7];
    const float* dt_b     = (const float*)d_in[8];
    const float* bp_w     = (const float*)d_in[9];
    const float* bp_b     = (const float*)d_in[10];
    const float* cp_w     = (const float*)d_in[11];
    const float* cp_b     = (const float*)d_in[12];
    const float* s2i_w    = (const float*)d_in[13];
    const float* s2i_b    = (const float*)d_in[14];
    const float* D_param  = (const float*)d_in[15];
    const float* out_w    = (const float*)d_in[16];
    const float* out_b    = (const float*)d_in[17];
    const float* gate_w   = (const float*)d_in[18];
    const float* gate_b   = (const float*)d_in[19];
    const float* e_w1     = (const float*)d_in[20];
    const float* e_b1     = (const float*)d_in[21];
    const float* e_w2     = (const float*)d_in[22];
    const float* e_b2     = (const float*)d_in[23];
    float* out = (float*)d_out;

    __half*  p_hh  = (__half*)symv(g_hh);
    float*   p_xz  = (float*)symv(g_xz);
    float*   p_xm  = (float*)symv(g_xm);
    __half*  p_xmh = (__half*)symv(g_xmh);
    float*   p_P   = (float*)symv(g_P);
    float*   p_y   = (float*)symv(g_y);
    __half*  p_yh  = (__half*)symv(g_yh);
    __half*  p_y2h = (__half*)symv(g_y2h);
    float*   p_x1  = (float*)symv(g_x1);
    __half*  p_h2h = (__half*)symv(g_h2h);
    float*   p_wf  = (float*)symv(g_wf);
    __half*  p_hid = (__half*)symv(g_hid);
    float*   p_eo  = (float*)symv(g_eo);
    __half2* p_wWp = (__half2*)symv(g_wWp);
    float*   p_bp  = (float*)symv(g_bp);
    __half2* p_wIn = (__half2*)symv(g_wIn);
    __half2* p_wS2i= (__half2*)symv(g_wS2i);
    __half2* p_wOut= (__half2*)symv(g_wOut);
    __half2* p_wE1 = (__half2*)symv(g_wE1);
    __half2* p_wE2 = (__half2*)symv(g_wE2);
    int*     p_idx = (int*)symv(g_idx);
    int*     p_cnt = (int*)symv(g_cnt);

    cudaFuncSetAttribute(gemm_fp16<0>, cudaFuncAttributeMaxDynamicSharedMemorySize, SMEM_BYTES);
    cudaFuncSetAttribute(gemm_fp16<2>, cudaFuncAttributeMaxDynamicSharedMemorySize, SMEM_BYTES);
    cudaFuncSetAttribute(gemm_fp16<5>, cudaFuncAttributeMaxDynamicSharedMemorySize, SMEM_BYTES);
    cudaFuncSetAttribute(gemm_fp16<6>, cudaFuncAttributeMaxDynamicSharedMemorySize, SMEM_BYTES);
    cudaFuncSetAttribute(gemm_fp16_s2i, cudaFuncAttributeMaxDynamicSharedMemorySize, SMEM_BYTES);

    // 0. weight prep
    pack_w_kernel<<<((INNER/2)*256 + 255)/256, 256>>>(dt_w, bp_w, cp_w, dt_b, bp_b, cp_b, p_wWp, p_bp);
    cvtw_kernel<<<((DD/2)*(2*INNER)/4 + 255)/256, 256>>>(in_proj_w, p_wIn, (DD/2)*(2*INNER), 2*INNER);
    cvtw_kernel<<<((DSTATE/2)*INNER/4 + 255)/256, 256>>>(s2i_w, p_wS2i, (DSTATE/2)*INNER, INNER);
    cvtw_kernel<<<((INNER/2)*DD/4 + 255)/256, 256>>>(out_w, p_wOut, (INNER/2)*DD, DD);
    cvtw_kernel<<<((EE*DD/2)*HID/4 + 255)/256, 256>>>(e_w1, p_wE1, (EE*DD/2)*HID, HID);
    cvtw_kernel<<<((EE*HID/2)*DD/4 + 255)/256, 256>>>(e_w2, p_wE2, (EE*HID/2)*DD, DD);

    // 1. rmsnorm(x) -> h (fp16)
    rmsnorm_kernel<<<MM, 256>>>(x, norm1_w, p_hh);

    // 2. xz = h @ in_proj_w + b  [4096,4096] K=1024
    gemm_fp16<0><<<dim3(2*INNER/128, MM/128, 1), 256, SMEM_BYTES>>>(p_hh, (const __half*)p_wIn, p_xz,
        MM, 2*INNER, DD, in_proj_b, 0, nullptr, 0, nullptr, nullptr, 0, 0, 0);

    // 3. conv + silu -> x_main (exact + fp16)
    conv_silu_kernel<<<(MM*INNER)/256, 256>>>(p_xz, conv_w, conv_b, p_xm, p_xmh);

    // 4. P = xmh @ Wp + bp  [4096,256] K=2048
    gemm_fp16<0><<<dim3(256/128, MM/128, 1), 256, SMEM_BYTES>>>(p_xmh, (const __half*)p_wWp, p_P,
        MM, 256, INNER, p_bp, 0, nullptr, 0, nullptr, nullptr, 0, 0, 0);

    // 5. selective scan -> y (float)
    scan_kernel<<<BB*DSTATE, 256>>>(p_P, p_y);

    // 6. layernorm over 64 -> yh (fp16)
    ln64_kernel<<<MM, 64>>>(p_y, p_yh);

    // 7. y2 = (y @ s2i_w + b + D*xm) * sigmoid(gate) -> fp16  K=64
    gemm_fp16_s2i<<<dim3(INNER/128, MM/128), 256, SMEM_BYTES>>>(p_yh, (const __half*)p_wS2i, p_y2h,
        MM, INNER, DSTATE, s2i_b, p_xm, D_param, p_xz + INNER, 2*INNER);

    // 8. x1 = x + (y2 @ out_w + b)  K=2048
    gemm_fp16<2><<<dim3(DD/128, MM/128, 1), 256, SMEM_BYTES>>>(p_y2h, (const __half*)p_wOut, p_x1,
        MM, DD, INNER, out_b, 0, x, DD, nullptr, nullptr, 0, 0, 0);

    // 9. rmsnorm2 + gating fused -> h2h (fp16), wf
    rms2_gate_kernel<<<MM, 256>>>(p_x1, norm2_w, gate_w, gate_b, p_h2h, p_wf);

    // 10. compaction -> idx/cnt
    compact_kernel<<<EE, 256>>>(p_wf, p_idx, p_cnt);

    // 11a. all experts, gelu GEMM in ONE launch (z = expert; shared A)
    gemm_fp16<5><<<dim3(HID/128, MM/128, EE), 256, SMEM_BYTES>>>(p_h2h, (const __half*)p_wE1, p_hid,
        MM, HID, DD, e_b1, HID, nullptr, 0, p_idx, p_cnt,
        0, (long long)DD*HID, (long long)MM*HID*2);

    // 11b. all experts, second GEMM in ONE launch (z = expert; per-expert A)
    gemm_fp16<6><<<dim3(DD/128, MM/128, EE), 256, SMEM_BYTES>>>(p_hid, (const __half*)p_wE2, p_eo,
        MM, DD, HID, e_b2, DD, nullptr, 0, p_idx, p_cnt,
        (long long)MM*HID, (long long)HID*DD, (long long)MM*DD*4);

    // 12. combine: out = x1 + sum_e wf*eo_e
    combine_kernel<<<MM, 256>>>(p_x1, p_wf, p_eo, out);
}

// round 16
// speedup vs baseline: 2.2415x; 1.0030x over previous
#include <cuda_runtime.h>
#include <cuda_fp16.h>
#include <math.h>

// ---------------- problem constants ----------------
#define BB 2
#define TT 2048
#define DD 1024
#define MM (BB*TT)          // 4096 token rows
#define INNER 2048
#define DSTATE 64
#define EE 4
#define HID 4096

// ---------------- scratch (device globals; no allocation allowed) ----------
__device__ __half g_hh  [MM*DD];        // rmsnorm1 output (fp16)
__device__ __half g_xzh [MM*2*INNER];   // in_proj output (fp16): x_main | gate
__device__ __half g_xmh [MM*INNER];     // conv+silu output (fp16)
__device__ float  g_P   [MM*256];       // packed dt|B|C projections (f32, feeds scan)
__device__ float  g_y   [MM*DSTATE];    // scan output (float)
__device__ __half g_yh  [MM*DSTATE];    // ln64 output (fp16)
__device__ __half g_y2h [MM*INNER];     // fp16
__device__ float  g_x1  [MM*DD];        // exact
__device__ __half g_h2h [MM*DD];        // fp16 (GEMM A)
__device__ float  g_wf  [MM*EE];
__device__ __half g_hid [(size_t)EE*MM*HID];   // per-expert fp16 hidden
__device__ float  g_eo  [(size_t)EE*MM*DD];    // per-expert dense expert outputs
__device__ int    g_idx [EE*MM];
__device__ int    g_cnt [EE];
// fp16 k-pair-interleaved weights: word[p*N+n] = {W[2p][n], W[2p+1][n]}
__device__ __half2 g_wWp [(INNER/2)*256];
__device__ float   g_bp  [256];
__device__ __half2 g_wIn [(DD/2)*(2*INNER)];
__device__ __half2 g_wS2i[(DSTATE/2)*INNER];
__device__ __half2 g_wOut[(INNER/2)*DD];
__device__ __half2 g_wE1 [(size_t)(EE*DD/2)*HID];
__device__ __half2 g_wE2 [(size_t)(EE*HID/2)*DD];

// ---------------- helpers ----------------
__device__ __forceinline__ float sigmoidf_(float x){ return 1.f/(1.f+expf(-x)); }
__device__ __forceinline__ void cpa16(unsigned dst, const void* src){
    asm volatile("cp.async.cg.shared.global [%0], [%1], 16;" :: "r"(dst), "l"(src));
}

// ---------------- weight conversion: f32 [K][N] -> half2 interleaved (x4) --
__global__ void cvtw_kernel(const float* __restrict__ W, __half2* __restrict__ out,
                            int nwords, int N)
{
    int i4 = (blockIdx.x*blockDim.x + threadIdx.x)*4;
    if (i4 >= nwords) return;
    int p = i4 / N, n = i4 - p*N;
    float4 a = *reinterpret_cast<const float4*>(&W[(size_t)(2*p)*N + n]);
    float4 b = *reinterpret_cast<const float4*>(&W[(size_t)(2*p+1)*N + n]);
    __half2 h[4];
    h[0] = __floats2half2_rn(a.x, b.x);
    h[1] = __floats2half2_rn(a.y, b.y);
    h[2] = __floats2half2_rn(a.z, b.z);
    h[3] = __floats2half2_rn(a.w, b.w);
    *reinterpret_cast<uint4*>(&out[i4]) = *reinterpret_cast<uint4*>(h);
}

// ---------------- rmsnorm (norm1): fp16 output ----------------
__global__ void rmsnorm_kernel(const float* __restrict__ x, const float* __restrict__ w,
                               __half* __restrict__ out_h)
{
    __shared__ float red[256];
    int row = blockIdx.x, tid = threadIdx.x;
    const float* xr = x + (size_t)row*DD;
    float s = 0.f;
    #pragma unroll
    for (int i = 0; i < DD/256; i++){ float v = xr[tid + i*256]; s += v*v; }
    red[tid] = s; __syncthreads();
    for (int off = 128; off > 0; off >>= 1){ if (tid < off) red[tid] += red[tid+off]; __syncthreads(); }
    float nr = rsqrtf(red[0]/(float)DD + 1e-6f);
    #pragma unroll
    for (int i = 0; i < DD/256; i++){
        int c = tid + i*256;
        out_h[(size_t)row*DD + c] = __float2half_rn(xr[c]*nr*w[c]);
    }
}

// ---------------- rmsnorm2 + gating fused (fp16 h2 + wf) -------------------
__global__ void rms2_gate_kernel(const float* __restrict__ x1, const float* __restrict__ w,
                                 const float* __restrict__ gw, const float* __restrict__ gb,
                                 __half* __restrict__ h2h, float* __restrict__ wf)
{
    __shared__ float red[256];
    __shared__ float4 red4[256];
    int row = blockIdx.x, tid = threadIdx.x;
    const float* xr = x1 + (size_t)row*DD;
    float s = 0.f;
    #pragma unroll
    for (int i = 0; i < DD/256; i++){ float v = xr[tid + i*256]; s += v*v; }
    red[tid] = s; __syncthreads();
    for (int off = 128; off > 0; off >>= 1){ if (tid < off) red[tid] += red[tid+off]; __syncthreads(); }
    float nr = rsqrtf(red[0]/(float)DD + 1e-6f);
    float p0=0.f,p1=0.f,p2=0.f,p3=0.f;
    #pragma unroll
    for (int i = 0; i < DD/256; i++){
        int c = tid + i*256;
        float v = xr[c]*nr*w[c];
        h2h[(size_t)row*DD + c] = __float2half_rn(v);
        const float* g = gw + c*4;
        p0 = fmaf(v, g[0], p0); p1 = fmaf(v, g[1], p1);
        p2 = fmaf(v, g[2], p2); p3 = fmaf(v, g[3], p3);
    }
    red4[tid] = make_float4(p0,p1,p2,p3); __syncthreads();
    for (int off = 128; off > 0; off >>= 1){
        if (tid < off){
            float4 a = red4[tid], b = red4[tid+off];
            red4[tid] = make_float4(a.x+b.x, a.y+b.y, a.z+b.z, a.w+b.w);
        }
        __syncthreads();
    }
    if (tid == 0){
        float l[4] = {red4[0].x+gb[0], red4[0].y+gb[1], red4[0].z+gb[2], red4[0].w+gb[3]};
        int i0 = 0;
        #pragma unroll
        for (int e=1;e<4;e++) if (l[e] > l[i0]) i0 = e;
        int i1 = -1;
        #pragma unroll
        for (int e=0;e<4;e++) if (e != i0 && (i1 < 0 || l[e] > l[i1])) i1 = e;
        float ex = expf(l[i1] - l[i0]);
        float q0 = 1.f/(1.f+ex), q1 = ex/(1.f+ex);
        float wv[4] = {0.f,0.f,0.f,0.f};
        wv[i0]=q0; wv[i1]=q1;
        #pragma unroll
        for (int e=0;e<4;e++) wf[(size_t)row*4+e]=wv[e];
    }
}

// ======= FP16 GEMM (m16n8k16), cp.async 3-stage, 128x128x64, 2 CTA/SM ======
// EPI: 0 bias->f32 | 2 residual->f32 | 7 bias->f16
//      5 gathered-A gelu->f16 (z = expert) | 6 scatter-store->f32 (z = expert)
#define KT 64                 // k-tile (halves)
#define AS_TH 72              // A row stride (halves)
#define AS_TW 36              // A row stride (words)
#define BS_TW 136             // B pair-row stride (words)
#define A_STAGE_B (128*AS_TH*2)   // 18432 B
#define B_STAGE_B (32*BS_TW*4)    // 17408 B
#define NSTAGE 3
#define SMEM_BYTES (NSTAGE*(A_STAGE_B + B_STAGE_B))   // 107520 B

template<int EPI>
__device__ __forceinline__ void epi_store(
    void* __restrict__ Cv, int row, int col, int N, float acc,
    const float* __restrict__ bias,
    const float* __restrict__ ep1, int ep_stride,
    const int* __restrict__ idx, int cnt)
{
    if ((EPI==5 || EPI==6) && row >= cnt) return;
    float v = acc + bias[col];
    if (EPI == 5) {
        v = 0.5f*v*(1.f + erff(v*0.70710678118654752f));
        ((__half*)Cv)[(size_t)row*N + col] = __float2half_rn(v);
    } else if (EPI == 6) {
        ((float*)Cv)[(size_t)idx[row]*N + col] = v;
    } else if (EPI == 2) {
        v += ep1[(size_t)row*ep_stride + col];
        ((float*)Cv)[(size_t)row*N + col] = v;
    } else if (EPI == 7) {
        ((__half*)Cv)[(size_t)row*N + col] = __float2half_rn(v);
    } else {
        ((float*)Cv)[(size_t)row*N + col] = v;
    }
}

// s2i epilogue: (acc + bias + D*xm) * sigmoid(gate) -> fp16 (xm/gate fp16)
__device__ __forceinline__ void epi_store1(
    __half* __restrict__ C, int row, int col, int N, float acc,
    const float* __restrict__ bias,
    const __half* __restrict__ xmh, const float* __restrict__ Dp,
    const __half* __restrict__ gateh, int ep_stride)
{
    float v = acc + bias[col];
    v += Dp[col]*__half2float(xmh[(size_t)row*N + col]);
    v *= sigmoidf_(__half2float(gateh[(size_t)row*ep_stride + col]));
    C[(size_t)row*N + col] = __float2half_rn(v);
}

template<int EPI>
__global__ void __launch_bounds__(256, 2) gemm_fp16(
    const __half* __restrict__ A, const __half* __restrict__ Bh,
    void* __restrict__ Cv, int M, int N, int K,
    const float* __restrict__ bias, int biasStride,
    const float* __restrict__ ep1, int ep_stride,
    const int* __restrict__ idx, const int* __restrict__ cnt_ptr,
    long long azStride, long long bzStride, long long czStrideBytes)
{
    extern __shared__ char smem[];
    int tid = threadIdx.x, lane = tid & 31, warp = tid >> 5;
    int wm = (warp >> 2)*64, wn = (warp & 3)*32;   // warp tile 64x32
    int rowBase = blockIdx.y*128, colBase = blockIdx.x*128;
    int ez = blockIdx.z;

    const __half* Az = A + (size_t)ez*azStride;
    const __half* Bz = Bh + (size_t)ez*bzStride;
    void* Cz = (char*)Cv + (size_t)ez*czStrideBytes;
    const float* biasz = bias + (size_t)ez*biasStride;
    const int* idxz = idx;

    int cnt = M;
    if (EPI==5 || EPI==6){
        cnt = cnt_ptr[ez];
        idxz = idx + (size_t)ez*MM;
        if (rowBase >= cnt) return;
    }

    // A fill: 128 rows x 64 halves; one row per 2 threads, 32 halves each
    int ar = tid >> 1;
    int acol = (tid & 1)*32;
    int arow_l = rowBase + ar;
    if (EPI==5 || EPI==6) arow_l = min(arow_l, cnt-1);
    int arow = (EPI==5) ? idxz[arow_l] : arow_l;
    const __half* aSrc = Az + (size_t)arow*K + acol;
    // B fill: 32 pair-rows x 256 halves; one row per 8 threads, 32 halves each
    int br = tid >> 3;
    int bcol = (tid & 7)*32;
    const __half* bSrc = Bz + (size_t)br*(2*N) + 2*colBase + bcol;

    unsigned asBase = (unsigned)__cvta_generic_to_shared(smem);
    unsigned bsBase = asBase + NSTAGE*A_STAGE_B;

    float acc[4][4][4];
    #pragma unroll
    for (int i=0;i<4;i++)
        #pragma unroll
        for (int j=0;j<4;j++)
            #pragma unroll
            for (int r=0;r<4;r++) acc[i][j][r]=0.f;

    int nk = K/KT;

    // prologue: stages 0,1
    #pragma unroll
    for (int s = 0; s < 2; s++){
        if (s < nk){
            unsigned ad = asBase + s*A_STAGE_B + (ar*AS_TH + acol)*2;
            const __half* as = aSrc + s*KT;
            cpa16(ad,    as);     cpa16(ad+16, as+8);
            cpa16(ad+32, as+16);  cpa16(ad+48, as+24);
            unsigned bd = bsBase + s*B_STAGE_B + br*(BS_TW*4) + bcol*2;
            const __half* bs = bSrc + (size_t)(s*32)*(2*N);
            cpa16(bd,    bs);     cpa16(bd+16, bs+8);
            cpa16(bd+32, bs+16);  cpa16(bd+48, bs+24);
            asm volatile("cp.async.commit_group;");
        }
    }

    for (int kt = 0; kt < nk; kt++){
        if (kt+2 < nk){
            int stg = (kt+2)%NSTAGE;
            unsigned ad = asBase + stg*A_STAGE_B + (ar*AS_TH + acol)*2;
            const __half* as = aSrc + (kt+2)*KT;
            cpa16(ad,    as);     cpa16(ad+16, as+8);
            cpa16(ad+32, as+16);  cpa16(ad+48, as+24);
            unsigned bd = bsBase + stg*B_STAGE_B + br*(BS_TW*4) + bcol*2;
            const __half* bs = bSrc + (size_t)((kt+2)*32)*(2*N);
            cpa16(bd,    bs);     cpa16(bd+16, bs+8);
            cpa16(bd+32, bs+16);  cpa16(bd+48, bs+24);
            asm volatile("cp.async.commit_group;");
            asm volatile("cp.async.wait_group 2;");
        } else if (kt+1 < nk){
            asm volatile("cp.async.wait_group 1;");
        } else {
            asm volatile("cp.async.wait_group 0;");
        }
        __syncthreads();

        int cur = kt % NSTAGE;
        const unsigned* AsW = (const unsigned*)(smem + cur*A_STAGE_B);
        const unsigned* BsW = (const unsigned*)(smem + NSTAGE*A_STAGE_B + cur*B_STAGE_B);

        #pragma unroll
        for (int kk = 0; kk < 32; kk += 8){          // pair units; 8 pairs = k16
            unsigned a[4][4], b[4][2];
            int cw = kk + (lane&3);
            #pragma unroll
            for (int i=0;i<4;i++){
                int r = wm + i*16 + (lane>>2);
                a[i][0] = AsW[r*AS_TW + cw];
                a[i][1] = AsW[(r+8)*AS_TW + cw];
                a[i][2] = AsW[r*AS_TW + cw + 4];
                a[i][3] = AsW[(r+8)*AS_TW + cw + 4];
            }
            #pragma unroll
            for (int j=0;j<4;j++){
                int cb = wn + j*8 + (lane>>2);
                b[j][0] = BsW[cw*BS_TW + cb];
                b[j][1] = BsW[(cw+4)*BS_TW + cb];
            }
            #pragma unroll
            for (int i=0;i<4;i++)
                #pragma unroll
                for (int j=0;j<4;j++){
                    asm volatile(
                        "mma.sync.aligned.m16n8k16.row.col.f32.f16.f16.f32 "
                        "{%0,%1,%2,%3}, {%4,%5,%6,%7}, {%8,%9}, {%0,%1,%2,%3};"
                        : "+f"(acc[i][j][0]), "+f"(acc[i][j][1]),
                          "+f"(acc[i][j][2]), "+f"(acc[i][j][3])
                        : "r"(a[i][0]), "r"(a[i][1]), "r"(a[i][2]), "r"(a[i][3]),
                          "r"(b[j][0]), "r"(b[j][1]));
                }
        }
        __syncthreads();
    }

    #pragma unroll
    for (int i=0;i<4;i++){
        #pragma unroll
        for (int j=0;j<4;j++){
            int r0 = rowBase + wm + i*16 + (lane>>2);
            int c0 = colBase + wn + j*8 + 2*(lane&3);
            epi_store<EPI>(Cz, r0,   c0,   N, acc[i][j][0], biasz, ep1, ep_stride, idxz, cnt);
            epi_store<EPI>(Cz, r0,   c0+1, N, acc[i][j][1], biasz, ep1, ep_stride, idxz, cnt);
            epi_store<EPI>(Cz, r0+8, c0,   N, acc[i][j][2], biasz, ep1, ep_stride, idxz, cnt);
            epi_store<EPI>(Cz, r0+8, c0+1, N, acc[i][j][3], biasz, ep1, ep_stride, idxz, cnt);
        }
    }
}

// Specialized s2i-gate GEMM: separate kernel (3 epilogue tensors)
__global__ void __launch_bounds__(256, 2) gemm_fp16_s2i(
    const __half* __restrict__ A, const __half* __restrict__ Bh,
    __half* __restrict__ C, int M, int N, int K,
    const float* __restrict__ bias,
    const __half* __restrict__ xmh, const float* __restrict__ Dp,
    const __half* __restrict__ gateh, int ep_stride)
{
    extern __shared__ char smem[];
    int tid = threadIdx.x, lane = tid & 31, warp = tid >> 5;
    int wm = (warp >> 2)*64, wn = (warp & 3)*32;
    int rowBase = blockIdx.y*128, colBase = blockIdx.x*128;

    int ar = tid >> 1;
    int acol = (tid & 1)*32;
    const __half* aSrc = A + (size_t)(rowBase + ar)*K + acol;
    int br = tid >> 3;
    int bcol = (tid & 7)*32;
    const __half* bSrc = Bh + (size_t)br*(2*N) + 2*colBase + bcol;

    unsigned asBase = (unsigned)__cvta_generic_to_shared(smem);
    unsigned bsBase = asBase + NSTAGE*A_STAGE_B;

    float acc[4][4][4];
    #pragma unroll
    for (int i=0;i<4;i++)
        #pragma unroll
        for (int j=0;j<4;j++)
            #pragma unroll
            for (int r=0;r<4;r++) acc[i][j][r]=0.f;

    int nk = K/KT;   // K=64 -> 1 tile
    #pragma unroll
    for (int s = 0; s < 2; s++){
        if (s < nk){
            unsigned ad = asBase + s*A_STAGE_B + (ar*AS_TH + acol)*2;
            const __half* as = aSrc + s*KT;
            cpa16(ad,    as);     cpa16(ad+16, as+8);
            cpa16(ad+32, as+16);  cpa16(ad+48, as+24);
            unsigned bd = bsBase + s*B_STAGE_B + br*(BS_TW*4) + bcol*2;
            const __half* bs = bSrc + (size_t)(s*32)*(2*N);
            cpa16(bd,    bs);     cpa16(bd+16, bs+8);
            cpa16(bd+32, bs+16);  cpa16(bd+48, bs+24);
            asm volatile("cp.async.commit_group;");
        }
    }
    for (int kt = 0; kt < nk; kt++){
        if (kt+1 < nk){ asm volatile("cp.async.wait_group 1;"); }
        else          { asm volatile("cp.async.wait_group 0;"); }
        __syncthreads();
        int cur = kt % NSTAGE;
        const unsigned* AsW = (const unsigned*)(smem + cur*A_STAGE_B);
        const unsigned* BsW = (const unsigned*)(smem + NSTAGE*A_STAGE_B + cur*B_STAGE_B);
        #pragma unroll
        for (int kk = 0; kk < 32; kk += 8){
            unsigned a[4][4], b[4][2];
            int cw = kk + (lane&3);
            #pragma unroll
            for (int i=0;i<4;i++){
                int r = wm + i*16 + (lane>>2);
                a[i][0] = AsW[r*AS_TW + cw];
                a[i][1] = AsW[(r+8)*AS_TW + cw];
                a[i][2] = AsW[r*AS_TW + cw + 4];
                a[i][3] = AsW[(r+8)*AS_TW + cw + 4];
            }
            #pragma unroll
            for (int j=0;j<4;j++){
                int cb = wn + j*8 + (lane>>2);
                b[j][0] = BsW[cw*BS_TW + cb];
                b[j][1] = BsW[(cw+4)*BS_TW + cb];
            }
            #pragma unroll
            for (int i=0;i<4;i++)
                #pragma unroll
                for (int j=0;j<4;j++){
                    asm volatile(
                        "mma.sync.aligned.m16n8k16.row.col.f32.f16.f16.f32 "
                        "{%0,%1,%2,%3}, {%4,%5,%6,%7}, {%8,%9}, {%0,%1,%2,%3};"
                        : "+f"(acc[i][j][0]), "+f"(acc[i][j][1]),
                          "+f"(acc[i][j][2]), "+f"(acc[i][j][3])
                        : "r"(a[i][0]), "r"(a[i][1]), "r"(a[i][2]), "r"(a[i][3]),
                          "r"(b[j][0]), "r"(b[j][1]));
                }
        }
        __syncthreads();
    }
    #pragma unroll
    for (int i=0;i<4;i++){
        #pragma unroll
        for (int j=0;j<4;j++){
            int r0 = rowBase + wm + i*16 + (lane>>2);
            int c0 = colBase + wn + j*8 + 2*(lane&3);
            epi_store1(C, r0,   c0,   N, acc[i][j][0], bias, xmh, Dp, gateh, ep_stride);
            epi_store1(C, r0,   c0+1, N, acc[i][j][1], bias, xmh, Dp, gateh, ep_stride);
            epi_store1(C, r0+8, c0,   N, acc[i][j][2], bias, xmh, Dp, gateh, ep_stride);
            epi_store1(C, r0+8, c0+1, N, acc[i][j][3], bias, xmh, Dp, gateh, ep_stride);
        }
    }
}

// ---------------- pack dt/B/C weights -> half2 interleaved [INNER/2][256] --
__global__ void pack_w_kernel(const float* __restrict__ dtw, const float* __restrict__ bpw,
                              const float* __restrict__ cpw, const float* __restrict__ dtb,
                              const float* __restrict__ bpb, const float* __restrict__ cpb,
                              __half2* __restrict__ W, float* __restrict__ bias)
{
    int i = blockIdx.x*blockDim.x + threadIdx.x;
    if (i >= (INNER/2)*256) return;
    int p = i >> 8, c = i & 255;
    float v0 = 0.f, v1 = 0.f;
    int k0 = 2*p, k1 = 2*p+1;
    if      (c < 64) { v0 = dtw[k0*64 + c];       v1 = dtw[k1*64 + c]; }
    else if (c < 128){ v0 = bpw[k0*64 + c - 64];  v1 = bpw[k1*64 + c - 64]; }
    else if (c < 192){ v0 = cpw[k0*64 + c - 128]; v1 = cpw[k1*64 + c - 128]; }
    W[i] = __floats2half2_rn(v0, v1);
    if (i < 256){
        float b = 0.f;
        if      (i < 64)  b = dtb[i];
        else if (i < 128) b = bpb[i-64];
        else if (i < 192) b = cpb[i-128];
        bias[i] = b;
    }
}

// ---------------- causal depthwise conv (K=3) + bias + silu (fp16 in/out) --
__global__ void conv_silu_kernel(const __half* __restrict__ xzh,
                                 const float* __restrict__ cw,
                                 const float* __restrict__ cb,
                                 __half* __restrict__ xmh)
{
    int idx = blockIdx.x*blockDim.x + threadIdx.x;
    if (idx >= MM*INNER) return;
    int c  = idx & (INNER-1);
    int rt = idx >> 11;
    int t  = rt & (TT-1);
    const float* w = cw + c*3;
    float v = w[2]*__half2float(xzh[(size_t)rt*(2*INNER) + c]);
    if (t >= 1) v += w[1]*__half2float(xzh[(size_t)(rt-1)*(2*INNER) + c]);
    if (t >= 2) v += w[0]*__half2float(xzh[(size_t)(rt-2)*(2*INNER) + c]);
    v += cb[c];
    float s = v * sigmoidf_(v);
    xmh[(size_t)rt*INNER + c] = __float2half_rn(s);
}

// ---------------- selective-scan over packed P [row,256] -------------------
__global__ void scan_kernel(const float* __restrict__ P, float* __restrict__ y)
{
    __shared__ float sA[256], sU[256];
    int bs = blockIdx.x;
    int b = bs >> 6, s = bs & 63;
    int tid = threadIdx.x;
    size_t baseP = (size_t)b*TT*256 + s;
    size_t baseY = (size_t)b*TT*DSTATE + s;
    float a_l[8], u_l[8], c_l[8];
    float A = 1.f, U = 0.f;
    #pragma unroll
    for (int i=0;i<8;i++){
        int t = tid*8 + i;
        size_t off = baseP + (size_t)t*256;
        float d  = sigmoidf_(P[off]);
        float bb = P[off + 64];
        c_l[i] = P[off + 128];
        float a = 1.f - d, u = d*bb;
        a_l[i]=a; u_l[i]=u;
        U = a*U + u;  A = a*A;
    }
    sA[tid]=A; sU[tid]=U; __syncthreads();
    for (int off=1; off<256; off<<=1){
        float pa=1.f, pu=0.f;
        if (tid >= off){ pa = sA[tid-off]; pu = sU[tid-off]; }
        __syncthreads();
        if (tid >= off){ U = A*pu + U; A = A*pa; }
        sA[tid]=A; sU[tid]=U; __syncthreads();
    }
    float state = (tid > 0) ? sU[tid-1] : 0.f;
    #pragma unroll
    for (int i=0;i<8;i++){
        state = a_l[i]*state + u_l[i];
        int t = tid*8 + i;
        y[baseY + (size_t)t*DSTATE] = c_l[i]*state;
    }
}

// ---------------- layernorm over dim 64 -> fp16 ----------------------------
__global__ void ln64_kernel(const float* __restrict__ y, __half* __restrict__ yh)
{
    __shared__ float red[64];
    __shared__ float mu_s, var_s;
    int row = blockIdx.x, tid = threadIdx.x;
    float v = y[(size_t)row*64 + tid];
    red[tid] = v; __syncthreads();
    for (int off=32; off>0; off>>=1){ if (tid<off) red[tid]+=red[tid+off]; __syncthreads(); }
    if (tid==0) mu_s = red[0]/64.f;
    __syncthreads();
    float d = v - mu_s;
    red[tid] = d*d; __syncthreads();
    for (int off=32; off>0; off>>=1){ if (tid<off) red[tid]+=red[tid+off]; __syncthreads(); }
    if (tid==0) var_s = red[0]/64.f;
    __syncthreads();
    yh[(size_t)row*64 + tid] = __float2half_rn(d * rsqrtf(var_s + 1e-5f));
}

// ---------------- per-expert row compaction (ballot scan) ------------------
__global__ void compact_kernel(const float* __restrict__ wf, int* __restrict__ idxs,
                               int* __restrict__ cnts)
{
    __shared__ int warp_sums[8];
    int e = blockIdx.x, tid = threadIdx.x;
    int lane = tid & 31, wid = tid >> 5;
    int base = 0;
    for (int chunk = 0; chunk < MM/256; chunk++){
        int row = chunk*256 + tid;
        int p = (wf[(size_t)row*4 + e] > 0.f) ? 1 : 0;
        unsigned m = __ballot_sync(0xffffffffu, p);
        int pre = __popc(m & ((1u << lane) - 1u));
        if (lane == 31) warp_sums[wid] = pre + p;
        __syncthreads();
        int wbase = 0, tot = 0;
        #pragma unroll
        for (int w = 0; w < 8; w++){
            int ws = warp_sums[w];
            if (w < wid) wbase += ws;
            tot += ws;
        }
        if (p) idxs[(size_t)e*MM + base + wbase + pre] = row;
        base += tot;
        __syncthreads();
    }
    if (tid == 0) cnts[e] = base;
}

// ---------------- combine: out = x1 + sum_e wf[e]*eo_e (float4) ------------
__global__ void combine_kernel(const float* __restrict__ x1, const float* __restrict__ wf,
                               const float* __restrict__ eo, float* __restrict__ out)
{
    int row = blockIdx.x, tid = threadIdx.x;   // 256 threads, DD/4 = 256
    float w0 = wf[(size_t)row*4+0], w1 = wf[(size_t)row*4+1];
    float w2 = wf[(size_t)row*4+2], w3 = wf[(size_t)row*4+3];
    size_t off4 = (size_t)row*(DD/4) + tid;
    float4 o = reinterpret_cast<const float4*>(x1)[off4];
    const size_t ez4 = (size_t)MM*(DD/4);
    if (w0 > 0.f){ float4 v = reinterpret_cast<const float4*>(eo)[off4];
        o.x += w0*v.x; o.y += w0*v.y; o.z += w0*v.z; o.w += w0*v.w; }
    if (w1 > 0.f){ float4 v = reinterpret_cast<const float4*>(eo)[ez4 + off4];
        o.x += w1*v.x; o.y += w1*v.y; o.z += w1*v.z; o.w += w1*v.w; }
    if (w2 > 0.f){ float4 v = reinterpret_cast<const float4*>(eo)[2*ez4 + off4];
        o.x += w2*v.x; o.y += w2*v.y; o.z += w2*v.z; o.w += w2*v.w; }
    if (w3 > 0.f){ float4 v = reinterpret_cast<const float4*>(eo)[3*ez4 + off4];
        o.x += w3*v.x; o.y += w3*v.y; o.z += w3*v.z; o.w += w3*v.w; }
    reinterpret_cast<float4*>(out)[off4] = o;
}

// ---------------- host launcher ----------------
static void* symv(const void* s){ void* p=nullptr; cudaGetSymbolAddress(&p, s); return p; }

extern "C" void kernel_launch(void* const* d_in, const int* in_sizes, int n_in,
                              void* d_out, int out_size)
{
    const float* x        = (const float*)d_in[0];
    const float* norm1_w  = (const float*)d_in[1];
    const float* norm2_w  = (const float*)d_in[2];
    const float* in_proj_w= (const float*)d_in[3];
    const float* in_proj_b= (const float*)d_in[4];
    const float* conv_w   = (const float*)d_in[5];
    const float* conv_b   = (const float*)d_in[6];
    const float* dt_w     = (const float*)d_in[7];
    const float* dt_b     = (const float*)d_in[8];
    const float* bp_w     = (const float*)d_in[9];
    const float* bp_b     = (const float*)d_in[10];
    const float* cp_w     = (const float*)d_in[11];
    const float* cp_b     = (const float*)d_in[12];
    const float* s2i_w    = (const float*)d_in[13];
    const float* s2i_b    = (const float*)d_in[14];
    const float* D_param  = (const float*)d_in[15];
    const float* out_w    = (const float*)d_in[16];
    const float* out_b    = (const float*)d_in[17];
    const float* gate_w   = (const float*)d_in[18];
    const float* gate_b   = (const float*)d_in[19];
    const float* e_w1     = (const float*)d_in[20];
    const float* e_b1     = (const float*)d_in[21];
    const float* e_w2     = (const float*)d_in[22];
    const float* e_b2     = (const float*)d_in[23];
    float* out = (float*)d_out;

    __half*  p_hh  = (__half*)symv(g_hh);
    __half*  p_xzh = (__half*)symv(g_xzh);
    __half*  p_xmh = (__half*)symv(g_xmh);
    float*   p_P   = (float*)symv(g_P);
    float*   p_y   = (float*)symv(g_y);
    __half*  p_yh  = (__half*)symv(g_yh);
    __half*  p_y2h = (__half*)symv(g_y2h);
    float*   p_x1  = (float*)symv(g_x1);
    __half*  p_h2h = (__half*)symv(g_h2h);
    float*   p_wf  = (float*)symv(g_wf);
    __half*  p_hid = (__half*)symv(g_hid);
    float*   p_eo  = (float*)symv(g_eo);
    __half2* p_wWp = (__half2*)symv(g_wWp);
    float*   p_bp  = (float*)symv(g_bp);
    __half2* p_wIn = (__half2*)symv(g_wIn);
    __half2* p_wS2i= (__half2*)symv(g_wS2i);
    __half2* p_wOut= (__half2*)symv(g_wOut);
    __half2* p_wE1 = (__half2*)symv(g_wE1);
    __half2* p_wE2 = (__half2*)symv(g_wE2);
    int*     p_idx = (int*)symv(g_idx);
    int*     p_cnt = (int*)symv(g_cnt);

    cudaFuncSetAttribute(gemm_fp16<0>, cudaFuncAttributeMaxDynamicSharedMemorySize, SMEM_BYTES);
    cudaFuncSetAttribute(gemm_fp16<2>, cudaFuncAttributeMaxDynamicSharedMemorySize, SMEM_BYTES);
    cudaFuncSetAttribute(gemm_fp16<5>, cudaFuncAttributeMaxDynamicSharedMemorySize, SMEM_BYTES);
    cudaFuncSetAttribute(gemm_fp16<6>, cudaFuncAttributeMaxDynamicSharedMemorySize, SMEM_BYTES);
    cudaFuncSetAttribute(gemm_fp16<7>, cudaFuncAttributeMaxDynamicSharedMemorySize, SMEM_BYTES);
    cudaFuncSetAttribute(gemm_fp16_s2i, cudaFuncAttributeMaxDynamicSharedMemorySize, SMEM_BYTES);

    // 0. weight prep
    pack_w_kernel<<<((INNER/2)*256 + 255)/256, 256>>>(dt_w, bp_w, cp_w, dt_b, bp_b, cp_b, p_wWp, p_bp);
    cvtw_kernel<<<((DD/2)*(2*INNER)/4 + 255)/256, 256>>>(in_proj_w, p_wIn, (DD/2)*(2*INNER), 2*INNER);
    cvtw_kernel<<<((DSTATE/2)*INNER/4 + 255)/256, 256>>>(s2i_w, p_wS2i, (DSTATE/2)*INNER, INNER);
    cvtw_kernel<<<((INNER/2)*DD/4 + 255)/256, 256>>>(out_w, p_wOut, (INNER/2)*DD, DD);
    cvtw_kernel<<<((EE*DD/2)*HID/4 + 255)/256, 256>>>(e_w1, p_wE1, (EE*DD/2)*HID, HID);
    cvtw_kernel<<<((EE*HID/2)*DD/4 + 255)/256, 256>>>(e_w2, p_wE2, (EE*HID/2)*DD, DD);

    // 1. rmsnorm(x) -> h (fp16)
    rmsnorm_kernel<<<MM, 256>>>(x, norm1_w, p_hh);

    // 2. xz = h @ in_proj_w + b -> fp16  [4096,4096] K=1024
    gemm_fp16<7><<<dim3(2*INNER/128, MM/128, 1), 256, SMEM_BYTES>>>(p_hh, (const __half*)p_wIn, p_xzh,
        MM, 2*INNER, DD, in_proj_b, 0, nullptr, 0, nullptr, nullptr, 0, 0, 0);

    // 3. conv + silu -> xmh (fp16)
    conv_silu_kernel<<<(MM*INNER)/256, 256>>>(p_xzh, conv_w, conv_b, p_xmh);

    // 4. P = xmh @ Wp + bp  [4096,256] K=2048 (f32 out, feeds scan)
    gemm_fp16<0><<<dim3(256/128, MM/128, 1), 256, SMEM_BYTES>>>(p_xmh, (const __half*)p_wWp, p_P,
        MM, 256, INNER, p_bp, 0, nullptr, 0, nullptr, nullptr, 0, 0, 0);

    // 5. selective scan -> y (float)
    scan_kernel<<<BB*DSTATE, 256>>>(p_P, p_y);

    // 6. layernorm over 64 -> yh (fp16)
    ln64_kernel<<<MM, 64>>>(p_y, p_yh);

    // 7. y2 = (y @ s2i_w + b + D*xm) * sigmoid(gate) -> fp16  K=64
    gemm_fp16_s2i<<<dim3(INNER/128, MM/128), 256, SMEM_BYTES>>>(p_yh, (const __half*)p_wS2i, p_y2h,
        MM, INNER, DSTATE, s2i_b, p_xmh, D_param, p_xzh + INNER, 2*INNER);

    // 8. x1 = x + (y2 @ out_w + b)  K=2048
    gemm_fp16<2><<<dim3(DD/128, MM/128, 1), 256, SMEM_BYTES>>>(p_y2h, (const __half*)p_wOut, p_x1,
        MM, DD, INNER, out_b, 0, x, DD, nullptr, nullptr, 0, 0, 0);

    // 9. rmsnorm2 + gating fused -> h2h (fp16), wf
    rms2_gate_kernel<<<MM, 256>>>(p_x1, norm2_w, gate_w, gate_b, p_h2h, p_wf);

    // 10. compaction -> idx/cnt
    compact_kernel<<<EE, 256>>>(p_wf, p_idx, p_cnt);

    // 11a. all experts, gelu GEMM in ONE launch (z = expert; shared A)
    gemm_fp16<5><<<dim3(HID/128, MM/128, EE), 256, SMEM_BYTES>>>(p_h2h, (const __half*)p_wE1, p_hid,
        MM, HID, DD, e_b1, HID, nullptr, 0, p_idx, p_cnt,
        0, (long long)DD*HID, (long long)MM*HID*2);

    // 11b. all experts, second GEMM in ONE launch (z = expert; per-expert A)
    gemm_fp16<6><<<dim3(DD/128, MM/128, EE), 256, SMEM_BYTES>>>(p_hid, (const __half*)p_wE2, p_eo,
        MM, DD, HID, e_b2, DD, nullptr, 0, p_idx, p_cnt,
        (long long)MM*HID, (long long)HID*DD, (long long)MM*DD*4);

    // 12. combine: out = x1 + sum_e wf*eo_e
    combine_kernel<<<MM, 256>>>(p_x1, p_wf, p_eo, out);
}